// round 2
// baseline (speedup 1.0000x reference)
#include <cuda_runtime.h>
#include <cuda_bf16.h>
#include <cstdint>

#define DEV_INLINE __device__ __forceinline__

// Scratch (allocation-free rule: __device__ globals)
__device__ float g_S1[10000 * 256];   // feature @ W1
__device__ float g_S2[10000 * 64];    // x1 @ W2

DEV_INLINE uint32_t smem_u32(const void* p) {
    return (uint32_t)__cvta_generic_to_shared(p);
}
DEV_INLINE void cp_async16(uint32_t dst, const void* src, bool pred) {
    int sz = pred ? 16 : 0;
    asm volatile("cp.async.cg.shared.global [%0], [%1], 16, %2;\n"
                 :: "r"(dst), "l"(src), "r"(sz));
}
DEV_INLINE void cp_commit() { asm volatile("cp.async.commit_group;\n" ::); }
template <int N> DEV_INLINE void cp_wait() {
    asm volatile("cp.async.wait_group %0;\n" :: "n"(N));
}

// Split two fp32 into packed bf16 (big) + packed bf16 (residual).
// bf16 -> f32 is an exact bit shift, so residual = x - upcast(big) is exact.
DEV_INLINE void split2(float x0, float x1, uint32_t& big, uint32_t& sml) {
    uint32_t b;
    asm("cvt.rn.bf16x2.f32 %0, %1, %2;" : "=r"(b) : "f"(x1), "f"(x0));
    float b0 = __uint_as_float(b << 16);
    float b1 = __uint_as_float(b & 0xFFFF0000u);
    float s0 = x0 - b0;
    float s1 = x1 - b1;
    uint32_t s;
    asm("cvt.rn.bf16x2.f32 %0, %1, %2;" : "=r"(s) : "f"(s1), "f"(s0));
    big = b; sml = s;
}

DEV_INLINE void mma_bf16(float* c, const uint32_t* a, const uint32_t* b) {
    asm volatile(
        "mma.sync.aligned.m16n8k16.row.col.f32.bf16.bf16.f32 "
        "{%0,%1,%2,%3}, {%4,%5,%6,%7}, {%8,%9}, {%0,%1,%2,%3};\n"
        : "+f"(c[0]), "+f"(c[1]), "+f"(c[2]), "+f"(c[3])
        : "r"(a[0]), "r"(a[1]), "r"(a[2]), "r"(a[3]), "r"(b[0]), "r"(b[1]));
}

// C[M,N] = A[M,K] @ B[K,N] (+bias) (relu?) — fp32 in/out, bf16x3 split MMA
// (acc += Ahi*Bhi + Ahi*Blo + Alo*Bhi; ~2^-16 effective precision).
// Requires: K % 16 == 0, N % BN == 0. M may be ragged.
template <int BM, int BN, int WARPS_M, int WARPS_N, bool RELU>
__global__ void __launch_bounds__(WARPS_M * WARPS_N * 32)
gemm_b3(const float* __restrict__ A, const float* __restrict__ B,
        const float* __restrict__ bias, float* __restrict__ C,
        int M, int N, int K)
{
    constexpr int BK = 16;
    constexpr int THREADS = WARPS_M * WARPS_N * 32;
    constexpr int WM = BM / WARPS_M;    // 32
    constexpr int WN = BN / WARPS_N;    // 64 (BN=128) or 32 (BN=64)
    constexpr int MT = WM / 16;
    constexpr int NT = WN / 8;
    constexpr int ASTR = BK + 4;        // 20: float2 frag loads stay 8B-aligned
    constexpr int BSTR = BN + 4;        // (k*BSTR+n)%32 distinct across quad -> conflict-free

    __shared__ float As[2][BM][ASTR];   // [m][k]
    __shared__ float Bs[2][BK][BSTR];   // [k][n]

    const int tid  = threadIdx.x;
    const int warp = tid >> 5;
    const int lane = tid & 31;
    const int wm = warp / WARPS_N;
    const int wn = warp % WARPS_N;
    const int g  = lane >> 2;   // 0..7
    const int tg = lane & 3;    // 0..3

    const int blockRow = blockIdx.x * BM;
    const int blockCol = blockIdx.y * BN;

    float acc[MT][NT][4];
    #pragma unroll
    for (int i = 0; i < MT; i++)
        #pragma unroll
        for (int j = 0; j < NT; j++)
            #pragma unroll
            for (int r = 0; r < 4; r++) acc[i][j][r] = 0.0f;

    auto load_tiles = [&](int kt, int stage) {
        const int k0 = kt * BK;
        // A tile: BM rows x 16 floats, 4x 16B chunks per row
        #pragma unroll
        for (int i = 0; i < (BM * 4) / THREADS; i++) {
            int c = tid + i * THREADS;
            int r = c >> 2, seg = c & 3;
            int grow = blockRow + r;
            bool ok = grow < M;
            int rclamp = ok ? grow : (M - 1);
            const float* src = A + (size_t)rclamp * K + k0 + seg * 4;
            cp_async16(smem_u32(&As[stage][r][seg * 4]), src, ok);
        }
        // B tile: BK rows x BN floats
        #pragma unroll
        for (int i = 0; i < (BK * BN / 4) / THREADS; i++) {
            int c = tid + i * THREADS;
            int r = c / (BN / 4), seg = c % (BN / 4);
            const float* src = B + (size_t)(k0 + r) * N + blockCol + seg * 4;
            cp_async16(smem_u32(&Bs[stage][r][seg * 4]), src, true);
        }
        cp_commit();
    };

    const int ktiles = K / BK;
    load_tiles(0, 0);

    for (int kt = 0; kt < ktiles; kt++) {
        const int stage = kt & 1;
        if (kt + 1 < ktiles) {
            load_tiles(kt + 1, stage ^ 1);
            cp_wait<1>();
        } else {
            cp_wait<0>();
        }
        __syncthreads();

        // One m16n8k16 k-step covers the whole BK=16 tile.
        uint32_t abig[MT][4], asml[MT][4];
        #pragma unroll
        for (int mt = 0; mt < MT; mt++) {
            int m = wm * WM + mt * 16;
            float2 a00 = *(const float2*)&As[stage][m + g    ][2 * tg    ];
            float2 a10 = *(const float2*)&As[stage][m + g + 8][2 * tg    ];
            float2 a01 = *(const float2*)&As[stage][m + g    ][2 * tg + 8];
            float2 a11 = *(const float2*)&As[stage][m + g + 8][2 * tg + 8];
            split2(a00.x, a00.y, abig[mt][0], asml[mt][0]);
            split2(a10.x, a10.y, abig[mt][1], asml[mt][1]);
            split2(a01.x, a01.y, abig[mt][2], asml[mt][2]);
            split2(a11.x, a11.y, abig[mt][3], asml[mt][3]);
        }
        #pragma unroll
        for (int nt = 0; nt < NT; nt++) {
            int n = wn * WN + nt * 8 + g;
            float b0 = Bs[stage][2 * tg    ][n];
            float b1 = Bs[stage][2 * tg + 1][n];
            float b2 = Bs[stage][2 * tg + 8][n];
            float b3 = Bs[stage][2 * tg + 9][n];
            uint32_t bbig[2], bsml[2];
            split2(b0, b1, bbig[0], bsml[0]);
            split2(b2, b3, bbig[1], bsml[1]);
            #pragma unroll
            for (int mt = 0; mt < MT; mt++) {
                mma_bf16(acc[mt][nt], abig[mt], bbig);
                mma_bf16(acc[mt][nt], abig[mt], bsml);
                mma_bf16(acc[mt][nt], asml[mt], bbig);
            }
        }
        __syncthreads();
    }

    // Epilogue: +bias, optional relu, guarded float2 stores
    #pragma unroll
    for (int mt = 0; mt < MT; mt++) {
        int r0 = blockRow + wm * WM + mt * 16 + g;
        int r1 = r0 + 8;
        #pragma unroll
        for (int nt = 0; nt < NT; nt++) {
            int col = blockCol + wn * WN + nt * 8 + 2 * tg;
            float2 bi = bias ? *(const float2*)(bias + col) : make_float2(0.f, 0.f);
            if (r0 < M) {
                float2 v = make_float2(acc[mt][nt][0] + bi.x, acc[mt][nt][1] + bi.y);
                if (RELU) { v.x = fmaxf(v.x, 0.f); v.y = fmaxf(v.y, 0.f); }
                *(float2*)(C + (size_t)r0 * N + col) = v;
            }
            if (r1 < M) {
                float2 v = make_float2(acc[mt][nt][2] + bi.x, acc[mt][nt][3] + bi.y);
                if (RELU) { v.x = fmaxf(v.x, 0.f); v.y = fmaxf(v.y, 0.f); }
                *(float2*)(C + (size_t)r1 * N + col) = v;
            }
        }
    }
}

// In-place row-wise log_softmax, N=64: one warp per row, 2 values per lane.
__global__ void log_softmax64(float* __restrict__ x, int M)
{
    int row = blockIdx.x * (blockDim.x >> 5) + (threadIdx.x >> 5);
    if (row >= M) return;
    int lane = threadIdx.x & 31;
    float* p = x + (size_t)row * 64;
    float v0 = p[lane], v1 = p[lane + 32];
    float mx = fmaxf(v0, v1);
    #pragma unroll
    for (int o = 16; o > 0; o >>= 1) mx = fmaxf(mx, __shfl_xor_sync(0xffffffffu, mx, o));
    float s = __expf(v0 - mx) + __expf(v1 - mx);
    #pragma unroll
    for (int o = 16; o > 0; o >>= 1) s += __shfl_xor_sync(0xffffffffu, s, o);
    float lse = mx + __logf(s);
    p[lane]      = v0 - lse;
    p[lane + 32] = v1 - lse;
}

extern "C" void kernel_launch(void* const* d_in, const int* in_sizes, int n_in,
                              void* d_out, int out_size)
{
    const float* feature = (const float*)d_in[0];
    const float* adj     = (const float*)d_in[1];
    const float* W1      = (const float*)d_in[2];
    const float* b1      = (const float*)d_in[3];
    const float* W2      = (const float*)d_in[4];
    const float* b2      = (const float*)d_in[5];

    const int hid  = in_sizes[3];              // 256
    const int ncls = in_sizes[5];              // 64
    const int fin  = in_sizes[2] / hid;        // 512
    const int n    = in_sizes[0] / fin;        // 10000

    float* s1; cudaGetSymbolAddress((void**)&s1, g_S1);
    float* s2; cudaGetSymbolAddress((void**)&s2, g_S2);

    float* x1   = (float*)d_out;               // [n, hid]
    float* out2 = x1 + (size_t)n * hid;        // [n, ncls]

    // 1) S1 = feature @ W1
    gemm_b3<128, 128, 4, 2, false>
        <<<dim3((n + 127) / 128, hid / 128), 256>>>(feature, W1, nullptr, s1, n, hid, fin);
    // 2) x1 = relu(adj @ S1 + b1)  -> d_out
    gemm_b3<128, 128, 4, 2, true>
        <<<dim3((n + 127) / 128, hid / 128), 256>>>(adj, s1, b1, x1, n, hid, n);
    // 3) S2 = x1 @ W2
    gemm_b3<64, 64, 2, 2, false>
        <<<dim3((n + 63) / 64, ncls / 64), 128>>>(x1, W2, nullptr, s2, n, ncls, hid);
    // 4) out2 = adj @ S2 + b2
    gemm_b3<64, 64, 2, 2, false>
        <<<dim3((n + 63) / 64, ncls / 64), 128>>>(adj, s2, b2, out2, n, ncls, n);
    // 5) log_softmax rows of out2 (in place)
    log_softmax64<<<(n + 7) / 8, 256>>>(out2, n);
}

// round 7
// speedup vs baseline: 1.2749x; 1.2749x over previous
#include <cuda_runtime.h>
#include <cuda_bf16.h>
#include <cstdint>

#define DEV_INLINE __device__ __forceinline__

// ------------------------- global scratch (no allocs allowed) -------------------------
__device__ __nv_bfloat16 g_W1T_hi[256 * 512],   g_W1T_lo[256 * 512];
__device__ __nv_bfloat16 g_W2T_hi[64 * 256],    g_W2T_lo[64 * 256];
__device__ __nv_bfloat16 g_S1T_hi[256 * 10000], g_S1T_lo[256 * 10000];
__device__ __nv_bfloat16 g_S2T_hi[64 * 10000],  g_S2T_lo[64 * 10000];
__device__ float g_P1[2 * 10000 * 256];   // GEMM2 split-K partials [s][m][n]
__device__ float g_P2[4 * 10000 * 64];    // GEMM4 split-K partials [s][m][n]

// ------------------------- helpers -------------------------
DEV_INLINE uint32_t smem_u32(const void* p) { return (uint32_t)__cvta_generic_to_shared(p); }

DEV_INLINE void cp_async16(uint32_t dst, const void* src, int bytes) {
    asm volatile("cp.async.cg.shared.global [%0], [%1], 16, %2;\n"
                 :: "r"(dst), "l"(src), "r"(bytes));
}
DEV_INLINE void cp_commit()  { asm volatile("cp.async.commit_group;\n" ::); }
DEV_INLINE void cp_wait_all(){ asm volatile("cp.async.wait_group 0;\n" ::); }

// fp32 pair -> packed bf16 hi + packed bf16 residual (hi upcast is an exact bitshift).
DEV_INLINE void split2(float x0, float x1, uint32_t& big, uint32_t& sml) {
    uint32_t b;
    asm("cvt.rn.bf16x2.f32 %0, %1, %2;" : "=r"(b) : "f"(x1), "f"(x0));
    float b0 = __uint_as_float(b << 16);
    float b1 = __uint_as_float(b & 0xFFFF0000u);
    uint32_t s;
    asm("cvt.rn.bf16x2.f32 %0, %1, %2;" : "=r"(s) : "f"(x1 - b1), "f"(x0 - b0));
    big = b; sml = s;
}

DEV_INLINE void mma_bf16(float* c, const uint32_t* a, const uint32_t* b) {
    asm volatile(
        "mma.sync.aligned.m16n8k16.row.col.f32.bf16.bf16.f32 "
        "{%0,%1,%2,%3}, {%4,%5,%6,%7}, {%8,%9}, {%0,%1,%2,%3};\n"
        : "+f"(c[0]), "+f"(c[1]), "+f"(c[2]), "+f"(c[3])
        : "r"(a[0]), "r"(a[1]), "r"(a[2]), "r"(a[3]), "r"(b[0]), "r"(b[1]));
}

// ------------------------- unified HMMA GEMM -------------------------
// D[m,n] = sum_k A[m,k]*BT[n,k]; A fp32 (split at STS), BT bf16 hi/lo [N][K] K-major.
// bf16x3 passes: Ahi*Bhi + Ahi*Blo + Alo*Bhi.
// grid: (mBlocks, nBlocks, kSlices).
// EPI 0: P[slice][m][Ntot] fp32.  EPI 1: Chi/Clo[n][m] bf16 (transposed, ld = M).
template <int BM, int BN, int WARPS_M, int WARPS_N, int EPI>
__global__ void __launch_bounds__(WARPS_M * WARPS_N * 32)
gemm_hmma(const float* __restrict__ A, int lda,
          const __nv_bfloat16* __restrict__ Bhi, const __nv_bfloat16* __restrict__ Blo, int ldb,
          int M, int K, int Ntot,
          float* __restrict__ P, __nv_bfloat16* __restrict__ Chi, __nv_bfloat16* __restrict__ Clo)
{
    constexpr int BK = 32;
    constexpr int THREADS = WARPS_M * WARPS_N * 32;
    constexpr int WM = BM / WARPS_M;       // 32
    constexpr int WN = BN / WARPS_N;       // 64 or 32
    constexpr int MT = WM / 16;            // 2
    constexpr int NT = WN / 8;             // 8 or 4
    constexpr int ROWB = 80;               // (BK+8) bf16 = 80 bytes/row, conflict-free frags
    constexpr int AB   = BM * ROWB;        // one A variant (hi or lo)
    constexpr int BB   = BN * ROWB;        // one B variant
    constexpr int OFF_ALO = AB;
    constexpr int OFF_BHI = 2 * AB;
    constexpr int STAGE = 2 * AB + 2 * BB;
    constexpr int NF4 = (BM * BK / 4) / THREADS;   // float4 A loads per thread
    constexpr int NBC = (BN * 4) / THREADS;        // B cp.async chunks per thread (per variant)

    extern __shared__ char sm[];
    const uint32_t smb = smem_u32(sm);

    const int tid  = threadIdx.x;
    const int warp = tid >> 5;
    const int lane = tid & 31;
    const int wm = warp / WARPS_N;
    const int wn = warp % WARPS_N;
    const int g  = lane >> 2;
    const int tg = lane & 3;

    const int m0 = blockIdx.x * BM;
    const int n0 = blockIdx.y * BN;
    Bhi += (size_t)n0 * ldb;
    Blo += (size_t)n0 * ldb;

    const int KS = gridDim.z, sl = blockIdx.z;
    const int nChTot = (K + BK - 1) / BK;
    const int cs = sl * nChTot / KS;
    const int ce = (sl + 1) * nChTot / KS;
    const int kB = cs * BK;
    const int kE = min(ce * BK, K);
    const int nCh = ce - cs;
    if (EPI == 0) P += (size_t)sl * M * Ntot;

    float acc[MT][NT][4];
    #pragma unroll
    for (int i = 0; i < MT; i++)
        #pragma unroll
        for (int j = 0; j < NT; j++)
            #pragma unroll
            for (int r = 0; r < 4; r++) acc[i][j][r] = 0.0f;

    float4 aReg[NF4];

    auto ldA = [&](int c) {
        const int k0 = kB + c * BK;
        #pragma unroll
        for (int i = 0; i < NF4; i++) {
            const int u = tid + i * THREADS;
            const int r = u >> 3, c4 = u & 7;
            const int mg = m0 + r, kg = k0 + c4 * 4;
            aReg[i] = (mg < M && kg < kE) ? *(const float4*)(A + (size_t)mg * lda + kg)
                                          : make_float4(0.f, 0.f, 0.f, 0.f);
        }
    };
    auto stA = [&](int s) {
        char* base = sm + s * STAGE;
        #pragma unroll
        for (int i = 0; i < NF4; i++) {
            const int u = tid + i * THREADS;
            const int r = u >> 3, c4 = u & 7;
            uint32_t h0, l0, h1, l1;
            split2(aReg[i].x, aReg[i].y, h0, l0);
            split2(aReg[i].z, aReg[i].w, h1, l1);
            const int off = r * ROWB + c4 * 8;
            *(uint2*)(base + off)            = make_uint2(h0, h1);
            *(uint2*)(base + OFF_ALO + off)  = make_uint2(l0, l1);
        }
    };
    auto ldB = [&](int c, int s) {
        const int k0 = kB + c * BK;
        #pragma unroll
        for (int i = 0; i < NBC; i++) {
            const int u = tid + i * THREADS;
            const int n = u >> 2, seg = u & 3;
            const int kk = k0 + seg * 8;
            const int by = (kk + 8 <= kE) ? 16 : 0;
            const uint32_t dst = smb + s * STAGE + OFF_BHI + n * ROWB + seg * 16;
            cp_async16(dst,      Bhi + (size_t)n * ldb + kk, by);
            cp_async16(dst + BB, Blo + (size_t)n * ldb + kk, by);
        }
        cp_commit();
    };

    // prologue: stage 0
    ldA(0);
    ldB(0, 0);
    cp_wait_all();
    stA(0);
    __syncthreads();

    for (int c = 0; c < nCh; c++) {
        const int s = c & 1;
        if (c + 1 < nCh) { ldA(c + 1); ldB(c + 1, s ^ 1); }

        const char* base = sm + s * STAGE;
        #pragma unroll
        for (int kk = 0; kk < BK; kk += 16) {
            uint32_t ah[MT][4], al[MT][4];
            #pragma unroll
            for (int mt = 0; mt < MT; mt++) {
                const int m = wm * WM + mt * 16;
                const int o00 = (m + g)     * ROWB + (kk + 2 * tg) * 2;
                const int o10 = (m + g + 8) * ROWB + (kk + 2 * tg) * 2;
                ah[mt][0] = *(const uint32_t*)(base + o00);
                ah[mt][1] = *(const uint32_t*)(base + o10);
                ah[mt][2] = *(const uint32_t*)(base + o00 + 16);
                ah[mt][3] = *(const uint32_t*)(base + o10 + 16);
                al[mt][0] = *(const uint32_t*)(base + OFF_ALO + o00);
                al[mt][1] = *(const uint32_t*)(base + OFF_ALO + o10);
                al[mt][2] = *(const uint32_t*)(base + OFF_ALO + o00 + 16);
                al[mt][3] = *(const uint32_t*)(base + OFF_ALO + o10 + 16);
            }
            #pragma unroll
            for (int nt = 0; nt < NT; nt++) {
                const int n = wn * WN + nt * 8 + g;
                const char* bb = base + OFF_BHI + n * ROWB + (kk + 2 * tg) * 2;
                uint32_t bh[2], bl[2];
                bh[0] = *(const uint32_t*)(bb);
                bh[1] = *(const uint32_t*)(bb + 16);
                bl[0] = *(const uint32_t*)(bb + BB);
                bl[1] = *(const uint32_t*)(bb + BB + 16);
                #pragma unroll
                for (int mt = 0; mt < MT; mt++) {
                    mma_bf16(acc[mt][nt], ah[mt], bh);
                    mma_bf16(acc[mt][nt], ah[mt], bl);
                    mma_bf16(acc[mt][nt], al[mt], bh);
                }
            }
        }

        if (c + 1 < nCh) { cp_wait_all(); stA(s ^ 1); }
        __syncthreads();
    }

    // ------------- epilogue -------------
    #pragma unroll
    for (int mt = 0; mt < MT; mt++) {
        const int r0 = m0 + wm * WM + mt * 16 + g;
        const int r1 = r0 + 8;
        #pragma unroll
        for (int nt = 0; nt < NT; nt++) {
            const int col = n0 + wn * WN + nt * 8 + 2 * tg;
            if (EPI == 0) {
                if (r0 < M) *(float2*)(P + (size_t)r0 * Ntot + col) = make_float2(acc[mt][nt][0], acc[mt][nt][1]);
                if (r1 < M) *(float2*)(P + (size_t)r1 * Ntot + col) = make_float2(acc[mt][nt][2], acc[mt][nt][3]);
            } else {
                if (r0 < M) {
                    const float v0 = acc[mt][nt][0], v1 = acc[mt][nt][1];
                    const __nv_bfloat16 h0 = __float2bfloat16(v0), h1 = __float2bfloat16(v1);
                    Chi[(size_t)col * M + r0]       = h0;
                    Chi[(size_t)(col + 1) * M + r0] = h1;
                    Clo[(size_t)col * M + r0]       = __float2bfloat16(v0 - __bfloat162float(h0));
                    Clo[(size_t)(col + 1) * M + r0] = __float2bfloat16(v1 - __bfloat162float(h1));
                }
                if (r1 < M) {
                    const float v0 = acc[mt][nt][2], v1 = acc[mt][nt][3];
                    const __nv_bfloat16 h0 = __float2bfloat16(v0), h1 = __float2bfloat16(v1);
                    Chi[(size_t)col * M + r1]       = h0;
                    Chi[(size_t)(col + 1) * M + r1] = h1;
                    Clo[(size_t)col * M + r1]       = __float2bfloat16(v0 - __bfloat162float(h0));
                    Clo[(size_t)(col + 1) * M + r1] = __float2bfloat16(v1 - __bfloat162float(h1));
                }
            }
        }
    }
}

// ------------------------- prep: W1/W2 -> transposed bf16 hi/lo -------------------------
__global__ void prep_weights(const float* __restrict__ W1, const float* __restrict__ W2)
{
    const int i = blockIdx.x * blockDim.x + threadIdx.x;
    if (i < 512 * 256) {
        const int k = i / 256, n = i % 256;
        const float v = W1[i];
        const __nv_bfloat16 h = __float2bfloat16(v);
        g_W1T_hi[n * 512 + k] = h;
        g_W1T_lo[n * 512 + k] = __float2bfloat16(v - __bfloat162float(h));
    }
    if (i < 256 * 64) {
        const int k = i / 64, n = i % 64;
        const float v = W2[i];
        const __nv_bfloat16 h = __float2bfloat16(v);
        g_W2T_hi[n * 256 + k] = h;
        g_W2T_lo[n * 256 + k] = __float2bfloat16(v - __bfloat162float(h));
    }
}

// ------------------------- reduce1: x1 = relu(sum_s P1 + b1) -------------------------
__global__ void reduce1(const float* __restrict__ b1, float* __restrict__ x1, int M, int KS)
{
    const int i = blockIdx.x * blockDim.x + threadIdx.x;   // float4 index
    const int tot = M * 64;                                // M*256/4
    if (i >= tot) return;
    const float4* P = (const float4*)g_P1;
    float4 v = P[i];
    for (int s = 1; s < KS; s++) {
        const float4 w = P[(size_t)s * tot + i];
        v.x += w.x; v.y += w.y; v.z += w.z; v.w += w.w;
    }
    const float4 b = ((const float4*)b1)[i & 63];
    v.x = fmaxf(v.x + b.x, 0.f); v.y = fmaxf(v.y + b.y, 0.f);
    v.z = fmaxf(v.z + b.z, 0.f); v.w = fmaxf(v.w + b.w, 0.f);
    ((float4*)x1)[i] = v;
}

// ------------------------- reduce2: out2 = log_softmax(sum_s P2 + b2) -------------------------
__global__ void reduce2(const float* __restrict__ b2, float* __restrict__ out2, int M, int KS)
{
    const int row = blockIdx.x * (blockDim.x >> 5) + (threadIdx.x >> 5);
    if (row >= M) return;
    const int lane = threadIdx.x & 31;
    const size_t tot = (size_t)M * 64;
    float v0 = 0.f, v1 = 0.f;
    for (int s = 0; s < KS; s++) {
        v0 += g_P2[s * tot + (size_t)row * 64 + lane];
        v1 += g_P2[s * tot + (size_t)row * 64 + lane + 32];
    }
    v0 += b2[lane]; v1 += b2[lane + 32];
    float mx = fmaxf(v0, v1);
    #pragma unroll
    for (int o = 16; o > 0; o >>= 1) mx = fmaxf(mx, __shfl_xor_sync(0xffffffffu, mx, o));
    float ssum = __expf(v0 - mx) + __expf(v1 - mx);
    #pragma unroll
    for (int o = 16; o > 0; o >>= 1) ssum += __shfl_xor_sync(0xffffffffu, ssum, o);
    const float lse = mx + __logf(ssum);
    out2[(size_t)row * 64 + lane]      = v0 - lse;
    out2[(size_t)row * 64 + lane + 32] = v1 - lse;
}

// ------------------------- host -------------------------
extern "C" void kernel_launch(void* const* d_in, const int* in_sizes, int n_in,
                              void* d_out, int out_size)
{
    const float* feature = (const float*)d_in[0];
    const float* adj     = (const float*)d_in[1];
    const float* W1      = (const float*)d_in[2];
    const float* b1      = (const float*)d_in[3];
    const float* W2      = (const float*)d_in[4];
    const float* b2      = (const float*)d_in[5];

    const int hid  = in_sizes[3];              // 256
    const int fin  = in_sizes[2] / hid;        // 512
    const int n    = in_sizes[0] / fin;        // 10000

    // smem: STAGE*2; STAGE = 2*BM*80 + 2*BN*80
    constexpr int SM_G1 = 2 * (2 * 128 * 80 + 2 * 128 * 80);  //  81920
    constexpr int SM_G2 = 2 * (2 * 128 * 80 + 2 * 256 * 80);  // 122880
    constexpr int SM_G4 = 2 * (2 * 128 * 80 + 2 * 64  * 80);  //  61440
    cudaFuncSetAttribute((const void*)gemm_hmma<128,128,4,2,1>, cudaFuncAttributeMaxDynamicSharedMemorySize, SM_G1);
    cudaFuncSetAttribute((const void*)gemm_hmma<128,256,4,4,0>, cudaFuncAttributeMaxDynamicSharedMemorySize, SM_G2);
    cudaFuncSetAttribute((const void*)gemm_hmma<128,64,4,2,1>,  cudaFuncAttributeMaxDynamicSharedMemorySize, SM_G4);
    cudaFuncSetAttribute((const void*)gemm_hmma<128,64,4,2,0>,  cudaFuncAttributeMaxDynamicSharedMemorySize, SM_G4);

    __nv_bfloat16 *w1h, *w1l, *w2h, *w2l, *s1h, *s1l, *s2h, *s2l;
    float *p1, *p2;
    cudaGetSymbolAddress((void**)&w1h, g_W1T_hi); cudaGetSymbolAddress((void**)&w1l, g_W1T_lo);
    cudaGetSymbolAddress((void**)&w2h, g_W2T_hi); cudaGetSymbolAddress((void**)&w2l, g_W2T_lo);
    cudaGetSymbolAddress((void**)&s1h, g_S1T_hi); cudaGetSymbolAddress((void**)&s1l, g_S1T_lo);
    cudaGetSymbolAddress((void**)&s2h, g_S2T_hi); cudaGetSymbolAddress((void**)&s2l, g_S2T_lo);
    cudaGetSymbolAddress((void**)&p1, g_P1);      cudaGetSymbolAddress((void**)&p2, g_P2);

    float* x1   = (float*)d_out;               // [n, 256]
    float* out2 = x1 + (size_t)n * hid;        // [n, 64]
    const int mb = (n + 127) / 128;            // 79

    // 0) weights -> transposed bf16 hi/lo
    prep_weights<<<512, 256>>>(W1, W2);
    // 1) S1T(hi/lo) = (feature @ W1)^T
    gemm_hmma<128,128,4,2,1><<<dim3(mb, 2, 1), 256, SM_G1>>>(
        feature, fin, w1h, w1l, fin, n, fin, hid, nullptr, s1h, s1l);
    // 2) P1[s] = adj @ S1 partials (split-K x2)
    gemm_hmma<128,256,4,4,0><<<dim3(mb, 1, 2), 512, SM_G2>>>(
        adj, n, s1h, s1l, n, n, n, hid, p1, nullptr, nullptr);
    // 3) x1 = relu(sum P1 + b1) -> d_out
    reduce1<<<(n * 64 + 255) / 256, 256>>>(b1, x1, n, 2);
    // 4) S2T(hi/lo) = (x1 @ W2)^T
    gemm_hmma<128,64,4,2,1><<<dim3(mb, 1, 1), 256, SM_G4>>>(
        x1, hid, w2h, w2l, hid, n, hid, 64, nullptr, s2h, s2l);
    // 5) P2[s] = adj @ S2 partials (split-K x4)
    gemm_hmma<128,64,4,2,0><<<dim3(mb, 1, 4), 256, SM_G4>>>(
        adj, n, s2h, s2l, n, n, n, 64, p2, nullptr, nullptr);
    // 6) out2 = log_softmax(sum P2 + b2) -> d_out
    reduce2<<<(n + 3) / 4, 128>>>(b2, out2, n, 4);
}

// round 8
// speedup vs baseline: 1.7046x; 1.3370x over previous
#include <cuda_runtime.h>
#include <cuda_bf16.h>
#include <cstdint>

#define DEV_INLINE __device__ __forceinline__

// ------------------------- global scratch (no allocs allowed) -------------------------
__device__ __nv_bfloat16 g_W1T_hi[256 * 512],   g_W1T_lo[256 * 512];
__device__ __nv_bfloat16 g_W2T_hi[64 * 256],    g_W2T_lo[64 * 256];
__device__ __nv_bfloat16 g_S1T_hi[256 * 10000], g_S1T_lo[256 * 10000];
__device__ __nv_bfloat16 g_S2T_hi[64 * 10000],  g_S2T_lo[64 * 10000];
__device__ float g_P1[8 * 10000 * 256];   // GEMM2 split-K partials [s][m][n]
__device__ float g_P2[4 * 10000 * 64];    // GEMM4 split-K partials [s][m][n]

// ------------------------- helpers -------------------------
DEV_INLINE uint32_t smem_u32(const void* p) { return (uint32_t)__cvta_generic_to_shared(p); }

DEV_INLINE void cp_async16(uint32_t dst, const void* src, int bytes) {
    asm volatile("cp.async.cg.shared.global [%0], [%1], 16, %2;\n"
                 :: "r"(dst), "l"(src), "r"(bytes));
}
DEV_INLINE void cp_commit()  { asm volatile("cp.async.commit_group;\n" ::); }
DEV_INLINE void cp_wait_all(){ asm volatile("cp.async.wait_group 0;\n" ::); }

// fp32 pair -> packed bf16 hi + packed bf16 residual (hi upcast is an exact bitshift).
DEV_INLINE void split2(float x0, float x1, uint32_t& big, uint32_t& sml) {
    uint32_t b;
    asm("cvt.rn.bf16x2.f32 %0, %1, %2;" : "=r"(b) : "f"(x1), "f"(x0));
    float b0 = __uint_as_float(b << 16);
    float b1 = __uint_as_float(b & 0xFFFF0000u);
    uint32_t s;
    asm("cvt.rn.bf16x2.f32 %0, %1, %2;" : "=r"(s) : "f"(x1 - b1), "f"(x0 - b0));
    big = b; sml = s;
}

DEV_INLINE void mma_bf16(float* c, const uint32_t* a, const uint32_t* b) {
    asm volatile(
        "mma.sync.aligned.m16n8k16.row.col.f32.bf16.bf16.f32 "
        "{%0,%1,%2,%3}, {%4,%5,%6,%7}, {%8,%9}, {%0,%1,%2,%3};\n"
        : "+f"(c[0]), "+f"(c[1]), "+f"(c[2]), "+f"(c[3])
        : "r"(a[0]), "r"(a[1]), "r"(a[2]), "r"(a[3]), "r"(b[0]), "r"(b[1]));
}

// ------------------------- unified HMMA GEMM -------------------------
// D[m,n] = sum_k A[m,k]*BT[n,k]; A fp32 (split at STS), BT bf16 hi/lo [N][K] K-major.
// bf16x3 passes: Ahi*Bhi + Ahi*Blo + Alo*Bhi.
// grid: (mBlocks, nBlocks, kSlices).
// EPI 0: P[slice][m][Ntot] fp32.  EPI 1: Chi/Clo[n][m] bf16 (transposed, ld = M).
template <int BM, int BN, int WARPS_M, int WARPS_N, int EPI>
__global__ void __launch_bounds__(WARPS_M * WARPS_N * 32)
gemm_hmma(const float* __restrict__ A, int lda,
          const __nv_bfloat16* __restrict__ Bhi, const __nv_bfloat16* __restrict__ Blo, int ldb,
          int M, int K, int Ntot,
          float* __restrict__ P, __nv_bfloat16* __restrict__ Chi, __nv_bfloat16* __restrict__ Clo)
{
    constexpr int BK = 32;
    constexpr int THREADS = WARPS_M * WARPS_N * 32;
    constexpr int WM = BM / WARPS_M;       // 32
    constexpr int WN = BN / WARPS_N;       // 64 or 32
    constexpr int MT = WM / 16;            // 2
    constexpr int NT = WN / 8;             // 8 or 4
    constexpr int ROWB = 80;               // (BK+8) bf16 = 80 bytes/row, conflict-free frags
    constexpr int AB   = BM * ROWB;        // one A variant (hi or lo)
    constexpr int BB   = BN * ROWB;        // one B variant
    constexpr int OFF_ALO = AB;
    constexpr int OFF_BHI = 2 * AB;
    constexpr int STAGE = 2 * AB + 2 * BB;
    constexpr int NF4 = (BM * BK / 4) / THREADS;   // float4 A loads per thread
    constexpr int NBC = (BN * 4) / THREADS;        // B cp.async chunks per thread (per variant)

    extern __shared__ char sm[];
    const uint32_t smb = smem_u32(sm);

    const int tid  = threadIdx.x;
    const int warp = tid >> 5;
    const int lane = tid & 31;
    const int wm = warp / WARPS_N;
    const int wn = warp % WARPS_N;
    const int g  = lane >> 2;
    const int tg = lane & 3;

    const int m0 = blockIdx.x * BM;
    const int n0 = blockIdx.y * BN;
    Bhi += (size_t)n0 * ldb;
    Blo += (size_t)n0 * ldb;

    const int KS = gridDim.z, sl = blockIdx.z;
    const int nChTot = (K + BK - 1) / BK;
    const int cs = sl * nChTot / KS;
    const int ce = (sl + 1) * nChTot / KS;
    const int kB = cs * BK;
    const int kE = min(ce * BK, K);
    const int nCh = ce - cs;
    if (EPI == 0) P += (size_t)sl * M * Ntot;

    float acc[MT][NT][4];
    #pragma unroll
    for (int i = 0; i < MT; i++)
        #pragma unroll
        for (int j = 0; j < NT; j++)
            #pragma unroll
            for (int r = 0; r < 4; r++) acc[i][j][r] = 0.0f;

    float4 aReg[NF4];

    auto ldA = [&](int c) {
        const int k0 = kB + c * BK;
        #pragma unroll
        for (int i = 0; i < NF4; i++) {
            const int u = tid + i * THREADS;
            const int r = u >> 3, c4 = u & 7;
            const int mg = m0 + r, kg = k0 + c4 * 4;
            aReg[i] = (mg < M && kg < kE) ? *(const float4*)(A + (size_t)mg * lda + kg)
                                          : make_float4(0.f, 0.f, 0.f, 0.f);
        }
    };
    auto stA = [&](int s) {
        char* base = sm + s * STAGE;
        #pragma unroll
        for (int i = 0; i < NF4; i++) {
            const int u = tid + i * THREADS;
            const int r = u >> 3, c4 = u & 7;
            uint32_t h0, l0, h1, l1;
            split2(aReg[i].x, aReg[i].y, h0, l0);
            split2(aReg[i].z, aReg[i].w, h1, l1);
            const int off = r * ROWB + c4 * 8;
            *(uint2*)(base + off)            = make_uint2(h0, h1);
            *(uint2*)(base + OFF_ALO + off)  = make_uint2(l0, l1);
        }
    };
    auto ldB = [&](int c, int s) {
        const int k0 = kB + c * BK;
        #pragma unroll
        for (int i = 0; i < NBC; i++) {
            const int u = tid + i * THREADS;
            const int n = u >> 2, seg = u & 3;
            const int kk = k0 + seg * 8;
            const int by = (kk + 8 <= kE) ? 16 : 0;
            const uint32_t dst = smb + s * STAGE + OFF_BHI + n * ROWB + seg * 16;
            cp_async16(dst,      Bhi + (size_t)n * ldb + kk, by);
            cp_async16(dst + BB, Blo + (size_t)n * ldb + kk, by);
        }
        cp_commit();
    };

    // prologue: stage 0
    ldA(0);
    ldB(0, 0);
    cp_wait_all();
    stA(0);
    __syncthreads();

    for (int c = 0; c < nCh; c++) {
        const int s = c & 1;
        if (c + 1 < nCh) { ldA(c + 1); ldB(c + 1, s ^ 1); }

        const char* base = sm + s * STAGE;
        #pragma unroll
        for (int kk = 0; kk < BK; kk += 16) {
            uint32_t ah[MT][4], al[MT][4];
            #pragma unroll
            for (int mt = 0; mt < MT; mt++) {
                const int m = wm * WM + mt * 16;
                const int o00 = (m + g)     * ROWB + (kk + 2 * tg) * 2;
                const int o10 = (m + g + 8) * ROWB + (kk + 2 * tg) * 2;
                ah[mt][0] = *(const uint32_t*)(base + o00);
                ah[mt][1] = *(const uint32_t*)(base + o10);
                ah[mt][2] = *(const uint32_t*)(base + o00 + 16);
                ah[mt][3] = *(const uint32_t*)(base + o10 + 16);
                al[mt][0] = *(const uint32_t*)(base + OFF_ALO + o00);
                al[mt][1] = *(const uint32_t*)(base + OFF_ALO + o10);
                al[mt][2] = *(const uint32_t*)(base + OFF_ALO + o00 + 16);
                al[mt][3] = *(const uint32_t*)(base + OFF_ALO + o10 + 16);
            }
            #pragma unroll
            for (int nt = 0; nt < NT; nt++) {
                const int n = wn * WN + nt * 8 + g;
                const char* bb = base + OFF_BHI + n * ROWB + (kk + 2 * tg) * 2;
                uint32_t bh[2], bl[2];
                bh[0] = *(const uint32_t*)(bb);
                bh[1] = *(const uint32_t*)(bb + 16);
                bl[0] = *(const uint32_t*)(bb + BB);
                bl[1] = *(const uint32_t*)(bb + BB + 16);
                #pragma unroll
                for (int mt = 0; mt < MT; mt++) {
                    mma_bf16(acc[mt][nt], ah[mt], bh);
                    mma_bf16(acc[mt][nt], ah[mt], bl);
                    mma_bf16(acc[mt][nt], al[mt], bh);
                }
            }
        }

        if (c + 1 < nCh) { cp_wait_all(); stA(s ^ 1); }
        __syncthreads();
    }

    // ------------- epilogue -------------
    #pragma unroll
    for (int mt = 0; mt < MT; mt++) {
        const int r0 = m0 + wm * WM + mt * 16 + g;
        const int r1 = r0 + 8;
        #pragma unroll
        for (int nt = 0; nt < NT; nt++) {
            const int col = n0 + wn * WN + nt * 8 + 2 * tg;
            if (EPI == 0) {
                if (r0 < M) *(float2*)(P + (size_t)r0 * Ntot + col) = make_float2(acc[mt][nt][0], acc[mt][nt][1]);
                if (r1 < M) *(float2*)(P + (size_t)r1 * Ntot + col) = make_float2(acc[mt][nt][2], acc[mt][nt][3]);
            } else {
                if (r0 < M) {
                    const float v0 = acc[mt][nt][0], v1 = acc[mt][nt][1];
                    const __nv_bfloat16 h0 = __float2bfloat16(v0), h1 = __float2bfloat16(v1);
                    Chi[(size_t)col * M + r0]       = h0;
                    Chi[(size_t)(col + 1) * M + r0] = h1;
                    Clo[(size_t)col * M + r0]       = __float2bfloat16(v0 - __bfloat162float(h0));
                    Clo[(size_t)(col + 1) * M + r0] = __float2bfloat16(v1 - __bfloat162float(h1));
                }
                if (r1 < M) {
                    const float v0 = acc[mt][nt][2], v1 = acc[mt][nt][3];
                    const __nv_bfloat16 h0 = __float2bfloat16(v0), h1 = __float2bfloat16(v1);
                    Chi[(size_t)col * M + r1]       = h0;
                    Chi[(size_t)(col + 1) * M + r1] = h1;
                    Clo[(size_t)col * M + r1]       = __float2bfloat16(v0 - __bfloat162float(h0));
                    Clo[(size_t)(col + 1) * M + r1] = __float2bfloat16(v1 - __bfloat162float(h1));
                }
            }
        }
    }
}

// ------------------------- prep: W1/W2 -> transposed bf16 hi/lo -------------------------
__global__ void prep_weights(const float* __restrict__ W1, const float* __restrict__ W2)
{
    const int i = blockIdx.x * blockDim.x + threadIdx.x;
    if (i < 512 * 256) {
        const int k = i / 256, n = i % 256;
        const float v = W1[i];
        const __nv_bfloat16 h = __float2bfloat16(v);
        g_W1T_hi[n * 512 + k] = h;
        g_W1T_lo[n * 512 + k] = __float2bfloat16(v - __bfloat162float(h));
    }
    if (i < 256 * 64) {
        const int k = i / 64, n = i % 64;
        const float v = W2[i];
        const __nv_bfloat16 h = __float2bfloat16(v);
        g_W2T_hi[n * 256 + k] = h;
        g_W2T_lo[n * 256 + k] = __float2bfloat16(v - __bfloat162float(h));
    }
}

// ------------------------- reduce1: x1 = relu(sum_s P1 + b1) -------------------------
__global__ void reduce1(const float* __restrict__ b1, float* __restrict__ x1, int M, int KS)
{
    const int i = blockIdx.x * blockDim.x + threadIdx.x;   // float4 index
    const int tot = M * 64;                                // M*256/4
    if (i >= tot) return;
    const float4* P = (const float4*)g_P1;
    float4 v = P[i];
    for (int s = 1; s < KS; s++) {
        const float4 w = P[(size_t)s * tot + i];
        v.x += w.x; v.y += w.y; v.z += w.z; v.w += w.w;
    }
    const float4 b = ((const float4*)b1)[i & 63];
    v.x = fmaxf(v.x + b.x, 0.f); v.y = fmaxf(v.y + b.y, 0.f);
    v.z = fmaxf(v.z + b.z, 0.f); v.w = fmaxf(v.w + b.w, 0.f);
    ((float4*)x1)[i] = v;
}

// ------------------------- reduce2: out2 = log_softmax(sum_s P2 + b2) -------------------------
__global__ void reduce2(const float* __restrict__ b2, float* __restrict__ out2, int M, int KS)
{
    const int row = blockIdx.x * (blockDim.x >> 5) + (threadIdx.x >> 5);
    if (row >= M) return;
    const int lane = threadIdx.x & 31;
    const size_t tot = (size_t)M * 64;
    float v0 = 0.f, v1 = 0.f;
    for (int s = 0; s < KS; s++) {
        v0 += g_P2[s * tot + (size_t)row * 64 + lane];
        v1 += g_P2[s * tot + (size_t)row * 64 + lane + 32];
    }
    v0 += b2[lane]; v1 += b2[lane + 32];
    float mx = fmaxf(v0, v1);
    #pragma unroll
    for (int o = 16; o > 0; o >>= 1) mx = fmaxf(mx, __shfl_xor_sync(0xffffffffu, mx, o));
    float ssum = __expf(v0 - mx) + __expf(v1 - mx);
    #pragma unroll
    for (int o = 16; o > 0; o >>= 1) ssum += __shfl_xor_sync(0xffffffffu, ssum, o);
    const float lse = mx + __logf(ssum);
    out2[(size_t)row * 64 + lane]      = v0 - lse;
    out2[(size_t)row * 64 + lane + 32] = v1 - lse;
}

// ------------------------- host -------------------------
extern "C" void kernel_launch(void* const* d_in, const int* in_sizes, int n_in,
                              void* d_out, int out_size)
{
    const float* feature = (const float*)d_in[0];
    const float* adj     = (const float*)d_in[1];
    const float* W1      = (const float*)d_in[2];
    const float* b1      = (const float*)d_in[3];
    const float* W2      = (const float*)d_in[4];
    const float* b2      = (const float*)d_in[5];

    const int hid  = in_sizes[3];              // 256
    const int fin  = in_sizes[2] / hid;        // 512
    const int n    = in_sizes[0] / fin;        // 10000

    // smem: STAGE*2; STAGE = 2*BM*80 + 2*BN*80
    constexpr int SM_G1 = 2 * (2 * 128 * 80 + 2 * 128 * 80);  //  81920
    constexpr int SM_G2 = 2 * (2 * 128 * 80 + 2 * 256 * 80);  // 122880
    constexpr int SM_G4 = 2 * (2 * 128 * 80 + 2 * 64  * 80);  //  61440
    cudaFuncSetAttribute((const void*)gemm_hmma<128,128,4,2,1>, cudaFuncAttributeMaxDynamicSharedMemorySize, SM_G1);
    cudaFuncSetAttribute((const void*)gemm_hmma<128,256,4,4,0>, cudaFuncAttributeMaxDynamicSharedMemorySize, SM_G2);
    cudaFuncSetAttribute((const void*)gemm_hmma<128,64,4,2,1>,  cudaFuncAttributeMaxDynamicSharedMemorySize, SM_G4);
    cudaFuncSetAttribute((const void*)gemm_hmma<128,64,4,2,0>,  cudaFuncAttributeMaxDynamicSharedMemorySize, SM_G4);

    __nv_bfloat16 *w1h, *w1l, *w2h, *w2l, *s1h, *s1l, *s2h, *s2l;
    float *p1, *p2;
    cudaGetSymbolAddress((void**)&w1h, g_W1T_hi); cudaGetSymbolAddress((void**)&w1l, g_W1T_lo);
    cudaGetSymbolAddress((void**)&w2h, g_W2T_hi); cudaGetSymbolAddress((void**)&w2l, g_W2T_lo);
    cudaGetSymbolAddress((void**)&s1h, g_S1T_hi); cudaGetSymbolAddress((void**)&s1l, g_S1T_lo);
    cudaGetSymbolAddress((void**)&s2h, g_S2T_hi); cudaGetSymbolAddress((void**)&s2l, g_S2T_lo);
    cudaGetSymbolAddress((void**)&p1, g_P1);      cudaGetSymbolAddress((void**)&p2, g_P2);

    float* x1   = (float*)d_out;               // [n, 256]
    float* out2 = x1 + (size_t)n * hid;        // [n, 64]
    const int mb = (n + 127) / 128;            // 79

    // 0) weights -> transposed bf16 hi/lo
    prep_weights<<<512, 256>>>(W1, W2);
    // 1) S1T(hi/lo) = (feature @ W1)^T
    gemm_hmma<128,128,4,2,1><<<dim3(mb, 2, 1), 256, SM_G1>>>(
        feature, fin, w1h, w1l, fin, n, fin, hid, nullptr, s1h, s1l);
    // 2) P1[s] = adj @ S1 partials (split-K x8 — 632 CTAs, 5 short waves)
    gemm_hmma<128,256,4,4,0><<<dim3(mb, 1, 8), 512, SM_G2>>>(
        adj, n, s1h, s1l, n, n, n, hid, p1, nullptr, nullptr);
    // 3) x1 = relu(sum P1 + b1) -> d_out
    reduce1<<<(n * 64 + 255) / 256, 256>>>(b1, x1, n, 8);
    // 4) S2T(hi/lo) = (x1 @ W2)^T
    gemm_hmma<128,64,4,2,1><<<dim3(mb, 1, 1), 256, SM_G4>>>(
        x1, hid, w2h, w2l, hid, n, hid, 64, nullptr, s2h, s2l);
    // 5) P2[s] = adj @ S2 partials (split-K x4)
    gemm_hmma<128,64,4,2,0><<<dim3(mb, 1, 4), 256, SM_G4>>>(
        adj, n, s2h, s2l, n, n, n, 64, p2, nullptr, nullptr);
    // 6) out2 = log_softmax(sum P2 + b2) -> d_out
    reduce2<<<(n + 3) / 4, 128>>>(b2, out2, n, 4);
}

// round 9
// speedup vs baseline: 1.8672x; 1.0954x over previous
#include <cuda_runtime.h>
#include <cuda_bf16.h>
#include <cstdint>

#define DEV_INLINE __device__ __forceinline__

// ------------------------- global scratch (no allocs allowed) -------------------------
__device__ __nv_bfloat16 g_W1T_hi[256 * 512],   g_W1T_lo[256 * 512];
__device__ __nv_bfloat16 g_W2T_hi[64 * 256],    g_W2T_lo[64 * 256];
__device__ __nv_bfloat16 g_S1T_hi[256 * 10000], g_S1T_lo[256 * 10000];
__device__ __nv_bfloat16 g_S2T_hi[64 * 10000],  g_S2T_lo[64 * 10000];
__device__ float g_P1[8 * 10000 * 256];   // GEMM2 split-K partials [s][m][n]
__device__ float g_P2[4 * 10000 * 64];    // GEMM4 split-K partials [s][m][n]

// ------------------------- helpers -------------------------
DEV_INLINE uint32_t smem_u32(const void* p) { return (uint32_t)__cvta_generic_to_shared(p); }

DEV_INLINE void cp_async16(uint32_t dst, const void* src, int bytes) {
    asm volatile("cp.async.cg.shared.global [%0], [%1], 16, %2;\n"
                 :: "r"(dst), "l"(src), "r"(bytes));
}
DEV_INLINE void cp_commit()  { asm volatile("cp.async.commit_group;\n" ::); }
DEV_INLINE void cp_wait_all(){ asm volatile("cp.async.wait_group 0;\n" ::); }

// fp32 pair -> packed bf16 hi + packed bf16 residual (hi upcast is an exact bitshift).
DEV_INLINE void split2(float x0, float x1, uint32_t& big, uint32_t& sml) {
    uint32_t b;
    asm("cvt.rn.bf16x2.f32 %0, %1, %2;" : "=r"(b) : "f"(x1), "f"(x0));
    float b0 = __uint_as_float(b << 16);
    float b1 = __uint_as_float(b & 0xFFFF0000u);
    uint32_t s;
    asm("cvt.rn.bf16x2.f32 %0, %1, %2;" : "=r"(s) : "f"(x1 - b1), "f"(x0 - b0));
    big = b; sml = s;
}

DEV_INLINE void mma_bf16(float* c, const uint32_t* a, const uint32_t* b) {
    asm volatile(
        "mma.sync.aligned.m16n8k16.row.col.f32.bf16.bf16.f32 "
        "{%0,%1,%2,%3}, {%4,%5,%6,%7}, {%8,%9}, {%0,%1,%2,%3};\n"
        : "+f"(c[0]), "+f"(c[1]), "+f"(c[2]), "+f"(c[3])
        : "r"(a[0]), "r"(a[1]), "r"(a[2]), "r"(a[3]), "r"(b[0]), "r"(b[1]));
}

DEV_INLINE void ldsm4(uint32_t addr, uint32_t& r0, uint32_t& r1, uint32_t& r2, uint32_t& r3) {
    asm volatile("ldmatrix.sync.aligned.m8n8.x4.shared.b16 {%0,%1,%2,%3}, [%4];"
                 : "=r"(r0), "=r"(r1), "=r"(r2), "=r"(r3) : "r"(addr));
}

// ------------------------- unified HMMA GEMM -------------------------
// D[m,n] = sum_k A[m,k]*BT[n,k]; A fp32 (split at STS), BT bf16 hi/lo [N][K] K-major.
// bf16x3 passes: Ahi*Bhi + Ahi*Blo + Alo*Bhi.  Fragments via ldmatrix.x4.
// grid: (mBlocks, nBlocks, kSlices).
// EPI 0: P[slice][m][Ntot] fp32.  EPI 1: Chi/Clo[n][m] bf16 (transposed, ld = M).
template <int BM, int BN, int WARPS_M, int WARPS_N, int EPI>
__global__ void __launch_bounds__(WARPS_M * WARPS_N * 32, 1)
gemm_hmma(const float* __restrict__ A, int lda,
          const __nv_bfloat16* __restrict__ Bhi, const __nv_bfloat16* __restrict__ Blo, int ldb,
          int M, int K, int Ntot,
          float* __restrict__ P, __nv_bfloat16* __restrict__ Chi, __nv_bfloat16* __restrict__ Clo)
{
    constexpr int BK = 32;
    constexpr int THREADS = WARPS_M * WARPS_N * 32;
    constexpr int WM = BM / WARPS_M;       // 64 (G2) or 32
    constexpr int WN = BN / WARPS_N;       // 64 or 32
    constexpr int MT = WM / 16;            // 4 or 2
    constexpr int NT = WN / 8;             // 8 or 4 (even; B ldsm handles nt pairs)
    constexpr int ROWB = 80;               // (BK+8) bf16: row starts hit banks 0,20,8,28,... conflict-free
    constexpr int AB   = BM * ROWB;
    constexpr int BB   = BN * ROWB;
    constexpr int OFF_ALO = AB;
    constexpr int OFF_BHI = 2 * AB;
    constexpr int STAGE = 2 * AB + 2 * BB;
    constexpr int NF4 = (BM * BK / 4) / THREADS;   // float4 A loads per thread
    constexpr int NBC = (BN * 4) / THREADS;        // B cp.async chunks per thread (per variant)

    extern __shared__ char sm[];
    const uint32_t smb = smem_u32(sm);

    const int tid  = threadIdx.x;
    const int warp = tid >> 5;
    const int lane = tid & 31;
    const int wm = warp / WARPS_N;
    const int wn = warp % WARPS_N;
    const int g  = lane >> 2;
    const int tg = lane & 3;

    // ldmatrix per-lane quad coordinates
    const int aq_m = (lane & 7) + ((lane >> 3) & 1) * 8;   // A: q0 m0-7,k0-7 | q1 m8-15,k0-7 | q2 m0-7,k8-15 | q3 m8-15,k8-15
    const int aq_k = ((lane >> 4) & 1) * 8;
    const int bq_n = (lane & 7) + ((lane >> 4) & 1) * 8;   // B: q0 n0-7,k0-7 | q1 n0-7,k8-15 | q2 n8-15,k0-7 | q3 n8-15,k8-15
    const int bq_k = ((lane >> 3) & 1) * 8;

    const int m0 = blockIdx.x * BM;
    const int n0 = blockIdx.y * BN;
    Bhi += (size_t)n0 * ldb;
    Blo += (size_t)n0 * ldb;

    const int KS = gridDim.z, sl = blockIdx.z;
    const int nChTot = (K + BK - 1) / BK;
    const int cs = sl * nChTot / KS;
    const int ce = (sl + 1) * nChTot / KS;
    const int kB = cs * BK;
    const int kE = min(ce * BK, K);
    const int nCh = ce - cs;
    if (EPI == 0) P += (size_t)sl * M * Ntot;

    float acc[MT][NT][4];
    #pragma unroll
    for (int i = 0; i < MT; i++)
        #pragma unroll
        for (int j = 0; j < NT; j++)
            #pragma unroll
            for (int r = 0; r < 4; r++) acc[i][j][r] = 0.0f;

    float4 aReg[NF4];

    auto ldA = [&](int c) {
        const int k0 = kB + c * BK;
        #pragma unroll
        for (int i = 0; i < NF4; i++) {
            const int u = tid + i * THREADS;
            const int r = u >> 3, c4 = u & 7;
            const int mg = m0 + r, kg = k0 + c4 * 4;
            aReg[i] = (mg < M && kg < kE) ? *(const float4*)(A + (size_t)mg * lda + kg)
                                          : make_float4(0.f, 0.f, 0.f, 0.f);
        }
    };
    auto stA = [&](int s) {
        char* base = sm + s * STAGE;
        #pragma unroll
        for (int i = 0; i < NF4; i++) {
            const int u = tid + i * THREADS;
            const int r = u >> 3, c4 = u & 7;
            uint32_t h0, l0, h1, l1;
            split2(aReg[i].x, aReg[i].y, h0, l0);
            split2(aReg[i].z, aReg[i].w, h1, l1);
            const int off = r * ROWB + c4 * 8;
            *(uint2*)(base + off)            = make_uint2(h0, h1);
            *(uint2*)(base + OFF_ALO + off)  = make_uint2(l0, l1);
        }
    };
    auto ldB = [&](int c, int s) {
        const int k0 = kB + c * BK;
        #pragma unroll
        for (int i = 0; i < NBC; i++) {
            const int u = tid + i * THREADS;
            const int n = u >> 2, seg = u & 3;
            const int kk = k0 + seg * 8;
            const int by = (kk + 8 <= kE) ? 16 : 0;
            const uint32_t dst = smb + s * STAGE + OFF_BHI + n * ROWB + seg * 16;
            cp_async16(dst,      Bhi + (size_t)n * ldb + kk, by);
            cp_async16(dst + BB, Blo + (size_t)n * ldb + kk, by);
        }
        cp_commit();
    };

    // prologue: stage 0
    ldA(0);
    ldB(0, 0);
    cp_wait_all();
    stA(0);
    __syncthreads();

    for (int c = 0; c < nCh; c++) {
        const int s = c & 1;
        if (c + 1 < nCh) { ldA(c + 1); ldB(c + 1, s ^ 1); }

        const uint32_t base = smb + s * STAGE;
        #pragma unroll
        for (int kk = 0; kk < BK; kk += 16) {
            // A fragments via ldmatrix.x4 (one per 16x16 tile, hi and lo)
            uint32_t ah[MT][4], al[MT][4];
            const uint32_t aAddr = base + (wm * WM + aq_m) * ROWB + (kk + aq_k) * 2;
            #pragma unroll
            for (int mt = 0; mt < MT; mt++) {
                ldsm4(aAddr + mt * 16 * ROWB,            ah[mt][0], ah[mt][1], ah[mt][2], ah[mt][3]);
                ldsm4(aAddr + mt * 16 * ROWB + OFF_ALO,  al[mt][0], al[mt][1], al[mt][2], al[mt][3]);
            }
            // B fragments: one ldsm.x4 covers an nt pair (16 n-rows x one kstep)
            const uint32_t bAddr = base + OFF_BHI + (wn * WN + bq_n) * ROWB + (kk + bq_k) * 2;
            #pragma unroll
            for (int p = 0; p < NT / 2; p++) {
                uint32_t bh[4], bl[4];
                ldsm4(bAddr + p * 16 * ROWB,      bh[0], bh[1], bh[2], bh[3]);
                ldsm4(bAddr + p * 16 * ROWB + BB, bl[0], bl[1], bl[2], bl[3]);
                #pragma unroll
                for (int h = 0; h < 2; h++) {
                    const int nt = 2 * p + h;
                    #pragma unroll
                    for (int mt = 0; mt < MT; mt++) {
                        mma_bf16(acc[mt][nt], ah[mt], bh + 2 * h);
                        mma_bf16(acc[mt][nt], ah[mt], bl + 2 * h);
                        mma_bf16(acc[mt][nt], al[mt], bh + 2 * h);
                    }
                }
            }
        }

        if (c + 1 < nCh) { cp_wait_all(); stA(s ^ 1); }
        __syncthreads();
    }

    // ------------- epilogue -------------
    #pragma unroll
    for (int mt = 0; mt < MT; mt++) {
        const int r0 = m0 + wm * WM + mt * 16 + g;
        const int r1 = r0 + 8;
        #pragma unroll
        for (int nt = 0; nt < NT; nt++) {
            const int col = n0 + wn * WN + nt * 8 + 2 * tg;
            if (EPI == 0) {
                if (r0 < M) *(float2*)(P + (size_t)r0 * Ntot + col) = make_float2(acc[mt][nt][0], acc[mt][nt][1]);
                if (r1 < M) *(float2*)(P + (size_t)r1 * Ntot + col) = make_float2(acc[mt][nt][2], acc[mt][nt][3]);
            } else {
                if (r0 < M) {
                    const float v0 = acc[mt][nt][0], v1 = acc[mt][nt][1];
                    const __nv_bfloat16 h0 = __float2bfloat16(v0), h1 = __float2bfloat16(v1);
                    Chi[(size_t)col * M + r0]       = h0;
                    Chi[(size_t)(col + 1) * M + r0] = h1;
                    Clo[(size_t)col * M + r0]       = __float2bfloat16(v0 - __bfloat162float(h0));
                    Clo[(size_t)(col + 1) * M + r0] = __float2bfloat16(v1 - __bfloat162float(h1));
                }
                if (r1 < M) {
                    const float v0 = acc[mt][nt][2], v1 = acc[mt][nt][3];
                    const __nv_bfloat16 h0 = __float2bfloat16(v0), h1 = __float2bfloat16(v1);
                    Chi[(size_t)col * M + r1]       = h0;
                    Chi[(size_t)(col + 1) * M + r1] = h1;
                    Clo[(size_t)col * M + r1]       = __float2bfloat16(v0 - __bfloat162float(h0));
                    Clo[(size_t)(col + 1) * M + r1] = __float2bfloat16(v1 - __bfloat162float(h1));
                }
            }
        }
    }
}

// ------------------------- prep: W1/W2 -> transposed bf16 hi/lo -------------------------
__global__ void prep_weights(const float* __restrict__ W1, const float* __restrict__ W2)
{
    const int i = blockIdx.x * blockDim.x + threadIdx.x;
    if (i < 512 * 256) {
        const int k = i / 256, n = i % 256;
        const float v = W1[i];
        const __nv_bfloat16 h = __float2bfloat16(v);
        g_W1T_hi[n * 512 + k] = h;
        g_W1T_lo[n * 512 + k] = __float2bfloat16(v - __bfloat162float(h));
    }
    if (i < 256 * 64) {
        const int k = i / 64, n = i % 64;
        const float v = W2[i];
        const __nv_bfloat16 h = __float2bfloat16(v);
        g_W2T_hi[n * 256 + k] = h;
        g_W2T_lo[n * 256 + k] = __float2bfloat16(v - __bfloat162float(h));
    }
}

// ------------------------- reduce1: x1 = relu(sum_s P1 + b1) -------------------------
__global__ void reduce1(const float* __restrict__ b1, float* __restrict__ x1, int M, int KS)
{
    const int i = blockIdx.x * blockDim.x + threadIdx.x;   // float4 index
    const int tot = M * 64;                                // M*256/4
    if (i >= tot) return;
    const float4* P = (const float4*)g_P1;
    float4 v = P[i];
    for (int s = 1; s < KS; s++) {
        const float4 w = P[(size_t)s * tot + i];
        v.x += w.x; v.y += w.y; v.z += w.z; v.w += w.w;
    }
    const float4 b = ((const float4*)b1)[i & 63];
    v.x = fmaxf(v.x + b.x, 0.f); v.y = fmaxf(v.y + b.y, 0.f);
    v.z = fmaxf(v.z + b.z, 0.f); v.w = fmaxf(v.w + b.w, 0.f);
    ((float4*)x1)[i] = v;
}

// ------------------------- reduce2: out2 = log_softmax(sum_s P2 + b2) -------------------------
__global__ void reduce2(const float* __restrict__ b2, float* __restrict__ out2, int M, int KS)
{
    const int row = blockIdx.x * (blockDim.x >> 5) + (threadIdx.x >> 5);
    if (row >= M) return;
    const int lane = threadIdx.x & 31;
    const size_t tot = (size_t)M * 64;
    float v0 = 0.f, v1 = 0.f;
    for (int s = 0; s < KS; s++) {
        v0 += g_P2[s * tot + (size_t)row * 64 + lane];
        v1 += g_P2[s * tot + (size_t)row * 64 + lane + 32];
    }
    v0 += b2[lane]; v1 += b2[lane + 32];
    float mx = fmaxf(v0, v1);
    #pragma unroll
    for (int o = 16; o > 0; o >>= 1) mx = fmaxf(mx, __shfl_xor_sync(0xffffffffu, mx, o));
    float ssum = __expf(v0 - mx) + __expf(v1 - mx);
    #pragma unroll
    for (int o = 16; o > 0; o >>= 1) ssum += __shfl_xor_sync(0xffffffffu, ssum, o);
    const float lse = mx + __logf(ssum);
    out2[(size_t)row * 64 + lane]      = v0 - lse;
    out2[(size_t)row * 64 + lane + 32] = v1 - lse;
}

// ------------------------- host -------------------------
extern "C" void kernel_launch(void* const* d_in, const int* in_sizes, int n_in,
                              void* d_out, int out_size)
{
    const float* feature = (const float*)d_in[0];
    const float* adj     = (const float*)d_in[1];
    const float* W1      = (const float*)d_in[2];
    const float* b1      = (const float*)d_in[3];
    const float* W2      = (const float*)d_in[4];
    const float* b2      = (const float*)d_in[5];

    const int hid  = in_sizes[3];              // 256
    const int fin  = in_sizes[2] / hid;        // 512
    const int n    = in_sizes[0] / fin;        // 10000

    // smem: STAGE*2; STAGE = 2*BM*80 + 2*BN*80
    constexpr int SM_G1 = 2 * (2 * 128 * 80 + 2 * 128 * 80);  //  81920
    constexpr int SM_G2 = 2 * (2 * 128 * 80 + 2 * 256 * 80);  // 122880
    constexpr int SM_G4 = 2 * (2 * 128 * 80 + 2 * 64  * 80);  //  61440
    cudaFuncSetAttribute((const void*)gemm_hmma<128,128,4,2,1>, cudaFuncAttributeMaxDynamicSharedMemorySize, SM_G1);
    cudaFuncSetAttribute((const void*)gemm_hmma<128,256,2,4,0>, cudaFuncAttributeMaxDynamicSharedMemorySize, SM_G2);
    cudaFuncSetAttribute((const void*)gemm_hmma<128,64,4,2,1>,  cudaFuncAttributeMaxDynamicSharedMemorySize, SM_G4);
    cudaFuncSetAttribute((const void*)gemm_hmma<128,64,4,2,0>,  cudaFuncAttributeMaxDynamicSharedMemorySize, SM_G4);

    __nv_bfloat16 *w1h, *w1l, *w2h, *w2l, *s1h, *s1l, *s2h, *s2l;
    float *p1, *p2;
    cudaGetSymbolAddress((void**)&w1h, g_W1T_hi); cudaGetSymbolAddress((void**)&w1l, g_W1T_lo);
    cudaGetSymbolAddress((void**)&w2h, g_W2T_hi); cudaGetSymbolAddress((void**)&w2l, g_W2T_lo);
    cudaGetSymbolAddress((void**)&s1h, g_S1T_hi); cudaGetSymbolAddress((void**)&s1l, g_S1T_lo);
    cudaGetSymbolAddress((void**)&s2h, g_S2T_hi); cudaGetSymbolAddress((void**)&s2l, g_S2T_lo);
    cudaGetSymbolAddress((void**)&p1, g_P1);      cudaGetSymbolAddress((void**)&p2, g_P2);

    float* x1   = (float*)d_out;               // [n, 256]
    float* out2 = x1 + (size_t)n * hid;        // [n, 64]
    const int mb = (n + 127) / 128;            // 79

    // 0) weights -> transposed bf16 hi/lo
    prep_weights<<<512, 256>>>(W1, W2);
    // 1) S1T(hi/lo) = (feature @ W1)^T
    gemm_hmma<128,128,4,2,1><<<dim3(mb, 2, 1), 256, SM_G1>>>(
        feature, fin, w1h, w1l, fin, n, fin, hid, nullptr, s1h, s1l);
    // 2) P1[s] = adj @ S1 partials (split-K x7 — 553 CTAs, 4 balanced waves; 64x64 warp tiles)
    gemm_hmma<128,256,2,4,0><<<dim3(mb, 1, 7), 256, SM_G2>>>(
        adj, n, s1h, s1l, n, n, n, hid, p1, nullptr, nullptr);
    // 3) x1 = relu(sum P1 + b1) -> d_out
    reduce1<<<(n * 64 + 255) / 256, 256>>>(b1, x1, n, 7);
    // 4) S2T(hi/lo) = (x1 @ W2)^T
    gemm_hmma<128,64,4,2,1><<<dim3(mb, 1, 1), 256, SM_G4>>>(
        x1, hid, w2h, w2l, hid, n, hid, 64, nullptr, s2h, s2l);
    // 5) P2[s] = adj @ S2 partials (split-K x4)
    gemm_hmma<128,64,4,2,0><<<dim3(mb, 1, 4), 256, SM_G4>>>(
        adj, n, s2h, s2l, n, n, n, 64, p2, nullptr, nullptr);
    // 6) out2 = log_softmax(sum P2 + b2) -> d_out
    reduce2<<<(n + 3) / 4, 128>>>(b2, out2, n, 4);
}

// round 10
// speedup vs baseline: 2.4346x; 1.3038x over previous
#include <cuda_runtime.h>
#include <cuda_fp16.h>
#include <cstdint>

#define DEV_INLINE __device__ __forceinline__

// ------------------------- global scratch (no allocs allowed) -------------------------
__device__ __half g_W1T_hi[256 * 512],  g_W1T_lo[256 * 512];
__device__ __half g_W2T_hi[64 * 256],   g_W2T_lo[64 * 256];
__device__ __half g_S1T[256 * 10000];         // S1^T single fp16
__device__ __half g_S2T[64 * 10000];          // S2^T single fp16
__device__ float  g_P1[8 * 10000 * 256];      // GEMM2 split-K partials [s][m][n] (scaled 2^14)
__device__ float  g_P2[4 * 10000 * 64];       // GEMM4 split-K partials [s][m][n] (scaled 2^14)

#define ADJ_SCALE 16384.0f
#define ADJ_INV   (1.0f / 16384.0f)

// ------------------------- helpers -------------------------
DEV_INLINE uint32_t smem_u32(const void* p) { return (uint32_t)__cvta_generic_to_shared(p); }

DEV_INLINE void cp_async16(uint32_t dst, const void* src, int bytes) {
    asm volatile("cp.async.cg.shared.global [%0], [%1], 16, %2;\n"
                 :: "r"(dst), "l"(src), "r"(bytes));
}
DEV_INLINE void cp_commit()  { asm volatile("cp.async.commit_group;\n" ::); }
DEV_INLINE void cp_wait_all(){ asm volatile("cp.async.wait_group 0;\n" ::); }

// fp32 pair -> packed fp16 hi + packed fp16 residual (scaled). hi+lo ~exact to 2^-22.
DEV_INLINE void split2h(float x0, float x1, float s, uint32_t& hh, uint32_t& ll) {
    const float y0 = x0 * s, y1 = x1 * s;
    const __half2 h = __floats2half2_rn(y0, y1);
    const float2 hf = __half22float2(h);
    const __half2 l = __floats2half2_rn(y0 - hf.x, y1 - hf.y);
    hh = *(const uint32_t*)&h;
    ll = *(const uint32_t*)&l;
}

DEV_INLINE void mma_f16(float* c, const uint32_t* a, const uint32_t* b) {
    asm volatile(
        "mma.sync.aligned.m16n8k16.row.col.f32.f16.f16.f32 "
        "{%0,%1,%2,%3}, {%4,%5,%6,%7}, {%8,%9}, {%0,%1,%2,%3};\n"
        : "+f"(c[0]), "+f"(c[1]), "+f"(c[2]), "+f"(c[3])
        : "r"(a[0]), "r"(a[1]), "r"(a[2]), "r"(a[3]), "r"(b[0]), "r"(b[1]));
}

DEV_INLINE void ldsm4(uint32_t addr, uint32_t& r0, uint32_t& r1, uint32_t& r2, uint32_t& r3) {
    asm volatile("ldmatrix.sync.aligned.m8n8.x4.shared.b16 {%0,%1,%2,%3}, [%4];"
                 : "=r"(r0), "=r"(r1), "=r"(r2), "=r"(r3) : "r"(addr));
}

// ------------------------- unified HMMA GEMM (fp16) -------------------------
// D[m,n] = sum_k (A[m,k]*scale) * BT[n,k].
// A fp32 -> fp16 hi/lo pair at STS.  BT fp16, K-major [N][K]:
//   PASSES==2: B single;        acc = Ah*B  + Al*B   (error = B fp16 trunc ~1.4e-4 rms)
//   PASSES==3: B hi/lo pair;    acc = Ah*Bh + Ah*Bl + Al*Bh  (~2^-21)
// grid: (mBlocks, nBlocks, kSlices).
// EPI 0: P[slice][m][Ntot] fp32.  EPI 1: C[n][m] single fp16 (transposed, ld = M).
template <int BM, int BN, int WARPS_M, int WARPS_N, int EPI, int PASSES>
__global__ void __launch_bounds__(WARPS_M * WARPS_N * 32, 1)
gemm_hmma(const float* __restrict__ A, int lda, float scale,
          const __half* __restrict__ Bhi, const __half* __restrict__ Blo, int ldb,
          int M, int K, int Ntot,
          float* __restrict__ P, __half* __restrict__ C)
{
    constexpr int BK = 32;
    constexpr int THREADS = WARPS_M * WARPS_N * 32;
    constexpr int WM = BM / WARPS_M;
    constexpr int WN = BN / WARPS_N;
    constexpr int MT = WM / 16;
    constexpr int NT = WN / 8;
    constexpr int ROWB = 80;               // (BK+8)*2B rows: starts hit banks 0,20,8,28,... conflict-free
    constexpr int AB   = BM * ROWB;
    constexpr int BB   = BN * ROWB;
    constexpr int OFF_ALO = AB;
    constexpr int OFF_BHI = 2 * AB;
    constexpr int STAGE = 2 * AB + (PASSES - 1) * BB;
    constexpr int NF4 = (BM * BK / 4) / THREADS;   // float4 A loads per thread
    constexpr int NBC = (BN * 4) / THREADS;        // B cp.async chunks per thread (per variant)

    extern __shared__ char sm[];
    const uint32_t smb = smem_u32(sm);

    const int tid  = threadIdx.x;
    const int warp = tid >> 5;
    const int lane = tid & 31;
    const int wm = warp / WARPS_N;
    const int wn = warp % WARPS_N;
    const int g  = lane >> 2;
    const int tg = lane & 3;

    // ldmatrix per-lane quad coordinates
    const int aq_m = (lane & 7) + ((lane >> 3) & 1) * 8;
    const int aq_k = ((lane >> 4) & 1) * 8;
    const int bq_n = (lane & 7) + ((lane >> 4) & 1) * 8;
    const int bq_k = ((lane >> 3) & 1) * 8;

    const int m0 = blockIdx.x * BM;
    const int n0 = blockIdx.y * BN;
    Bhi += (size_t)n0 * ldb;
    if (PASSES == 3) Blo += (size_t)n0 * ldb;

    const int KS = gridDim.z, sl = blockIdx.z;
    const int nChTot = (K + BK - 1) / BK;
    const int cs = sl * nChTot / KS;
    const int ce = (sl + 1) * nChTot / KS;
    const int kB = cs * BK;
    const int kE = min(ce * BK, K);
    const int nCh = ce - cs;
    if (EPI == 0) P += (size_t)sl * M * Ntot;

    float acc[MT][NT][4];
    #pragma unroll
    for (int i = 0; i < MT; i++)
        #pragma unroll
        for (int j = 0; j < NT; j++)
            #pragma unroll
            for (int r = 0; r < 4; r++) acc[i][j][r] = 0.0f;

    float4 aReg[NF4];

    auto ldA = [&](int c) {
        const int k0 = kB + c * BK;
        #pragma unroll
        for (int i = 0; i < NF4; i++) {
            const int u = tid + i * THREADS;
            const int r = u >> 3, c4 = u & 7;
            const int mg = m0 + r, kg = k0 + c4 * 4;
            aReg[i] = (mg < M && kg < kE) ? *(const float4*)(A + (size_t)mg * lda + kg)
                                          : make_float4(0.f, 0.f, 0.f, 0.f);
        }
    };
    auto stA = [&](int s) {
        char* base = sm + s * STAGE;
        #pragma unroll
        for (int i = 0; i < NF4; i++) {
            const int u = tid + i * THREADS;
            const int r = u >> 3, c4 = u & 7;
            uint32_t h0, l0, h1, l1;
            split2h(aReg[i].x, aReg[i].y, scale, h0, l0);
            split2h(aReg[i].z, aReg[i].w, scale, h1, l1);
            const int off = r * ROWB + c4 * 8;
            *(uint2*)(base + off)            = make_uint2(h0, h1);
            *(uint2*)(base + OFF_ALO + off)  = make_uint2(l0, l1);
        }
    };
    auto ldB = [&](int c, int s) {
        const int k0 = kB + c * BK;
        #pragma unroll
        for (int i = 0; i < NBC; i++) {
            const int u = tid + i * THREADS;
            const int n = u >> 2, seg = u & 3;
            const int kk = k0 + seg * 8;
            const int by = (kk + 8 <= kE) ? 16 : 0;
            const uint32_t dst = smb + s * STAGE + OFF_BHI + n * ROWB + seg * 16;
            cp_async16(dst, Bhi + (size_t)n * ldb + kk, by);
            if (PASSES == 3)
                cp_async16(dst + BB, Blo + (size_t)n * ldb + kk, by);
        }
        cp_commit();
    };

    // prologue: stage 0
    ldA(0);
    ldB(0, 0);
    cp_wait_all();
    stA(0);
    __syncthreads();

    for (int c = 0; c < nCh; c++) {
        const int s = c & 1;
        if (c + 1 < nCh) { ldA(c + 1); ldB(c + 1, s ^ 1); }

        const uint32_t base = smb + s * STAGE;
        #pragma unroll
        for (int kk = 0; kk < BK; kk += 16) {
            uint32_t ah[MT][4], al[MT][4];
            const uint32_t aAddr = base + (wm * WM + aq_m) * ROWB + (kk + aq_k) * 2;
            #pragma unroll
            for (int mt = 0; mt < MT; mt++) {
                ldsm4(aAddr + mt * 16 * ROWB,            ah[mt][0], ah[mt][1], ah[mt][2], ah[mt][3]);
                ldsm4(aAddr + mt * 16 * ROWB + OFF_ALO,  al[mt][0], al[mt][1], al[mt][2], al[mt][3]);
            }
            const uint32_t bAddr = base + OFF_BHI + (wn * WN + bq_n) * ROWB + (kk + bq_k) * 2;
            #pragma unroll
            for (int p = 0; p < NT / 2; p++) {
                uint32_t bh[4];
                ldsm4(bAddr + p * 16 * ROWB, bh[0], bh[1], bh[2], bh[3]);
                if (PASSES == 3) {
                    uint32_t bl[4];
                    ldsm4(bAddr + p * 16 * ROWB + BB, bl[0], bl[1], bl[2], bl[3]);
                    #pragma unroll
                    for (int h = 0; h < 2; h++) {
                        const int nt = 2 * p + h;
                        #pragma unroll
                        for (int mt = 0; mt < MT; mt++) {
                            mma_f16(acc[mt][nt], ah[mt], bh + 2 * h);
                            mma_f16(acc[mt][nt], ah[mt], bl + 2 * h);
                            mma_f16(acc[mt][nt], al[mt], bh + 2 * h);
                        }
                    }
                } else {
                    #pragma unroll
                    for (int h = 0; h < 2; h++) {
                        const int nt = 2 * p + h;
                        #pragma unroll
                        for (int mt = 0; mt < MT; mt++) {
                            mma_f16(acc[mt][nt], ah[mt], bh + 2 * h);
                            mma_f16(acc[mt][nt], al[mt], bh + 2 * h);
                        }
                    }
                }
            }
        }

        if (c + 1 < nCh) { cp_wait_all(); stA(s ^ 1); }
        __syncthreads();
    }

    // ------------- epilogue -------------
    #pragma unroll
    for (int mt = 0; mt < MT; mt++) {
        const int r0 = m0 + wm * WM + mt * 16 + g;
        const int r1 = r0 + 8;
        #pragma unroll
        for (int nt = 0; nt < NT; nt++) {
            const int col = n0 + wn * WN + nt * 8 + 2 * tg;
            if (EPI == 0) {
                if (r0 < M) *(float2*)(P + (size_t)r0 * Ntot + col) = make_float2(acc[mt][nt][0], acc[mt][nt][1]);
                if (r1 < M) *(float2*)(P + (size_t)r1 * Ntot + col) = make_float2(acc[mt][nt][2], acc[mt][nt][3]);
            } else {
                if (r0 < M) {
                    C[(size_t)col * M + r0]       = __float2half(acc[mt][nt][0]);
                    C[(size_t)(col + 1) * M + r0] = __float2half(acc[mt][nt][1]);
                }
                if (r1 < M) {
                    C[(size_t)col * M + r1]       = __float2half(acc[mt][nt][2]);
                    C[(size_t)(col + 1) * M + r1] = __float2half(acc[mt][nt][3]);
                }
            }
        }
    }
}

// ------------------------- prep: W1/W2 -> transposed fp16 hi/lo -------------------------
__global__ void prep_weights(const float* __restrict__ W1, const float* __restrict__ W2)
{
    const int i = blockIdx.x * blockDim.x + threadIdx.x;
    if (i < 512 * 256) {
        const int k = i / 256, n = i % 256;
        const float v = W1[i];
        const __half h = __float2half_rn(v);
        g_W1T_hi[n * 512 + k] = h;
        g_W1T_lo[n * 512 + k] = __float2half_rn(v - __half2float(h));
    }
    if (i < 256 * 64) {
        const int k = i / 64, n = i % 64;
        const float v = W2[i];
        const __half h = __float2half_rn(v);
        g_W2T_hi[n * 64 * 0 + n * 256 + k - n * 0] = h;   // n*256 + k
        g_W2T_lo[n * 256 + k] = __float2half_rn(v - __half2float(h));
    }
}

// ------------------------- reduce1: x1 = relu(inv*sum_s P1 + b1) -------------------------
__global__ void reduce1(const float* __restrict__ b1, float* __restrict__ x1, int M, int KS)
{
    const int i = blockIdx.x * blockDim.x + threadIdx.x;   // float4 index
    const int tot = M * 64;                                // M*256/4
    if (i >= tot) return;
    const float4* P = (const float4*)g_P1;
    float4 v = P[i];
    for (int s = 1; s < KS; s++) {
        const float4 w = P[(size_t)s * tot + i];
        v.x += w.x; v.y += w.y; v.z += w.z; v.w += w.w;
    }
    const float4 b = ((const float4*)b1)[i & 63];
    v.x = fmaxf(v.x * ADJ_INV + b.x, 0.f); v.y = fmaxf(v.y * ADJ_INV + b.y, 0.f);
    v.z = fmaxf(v.z * ADJ_INV + b.z, 0.f); v.w = fmaxf(v.w * ADJ_INV + b.w, 0.f);
    ((float4*)x1)[i] = v;
}

// ------------------------- reduce2: out2 = log_softmax(inv*sum_s P2 + b2) -------------------------
__global__ void reduce2(const float* __restrict__ b2, float* __restrict__ out2, int M, int KS)
{
    const int row = blockIdx.x * (blockDim.x >> 5) + (threadIdx.x >> 5);
    if (row >= M) return;
    const int lane = threadIdx.x & 31;
    const size_t tot = (size_t)M * 64;
    float v0 = 0.f, v1 = 0.f;
    for (int s = 0; s < KS; s++) {
        v0 += g_P2[s * tot + (size_t)row * 64 + lane];
        v1 += g_P2[s * tot + (size_t)row * 64 + lane + 32];
    }
    v0 = v0 * ADJ_INV + b2[lane];
    v1 = v1 * ADJ_INV + b2[lane + 32];
    float mx = fmaxf(v0, v1);
    #pragma unroll
    for (int o = 16; o > 0; o >>= 1) mx = fmaxf(mx, __shfl_xor_sync(0xffffffffu, mx, o));
    float ssum = __expf(v0 - mx) + __expf(v1 - mx);
    #pragma unroll
    for (int o = 16; o > 0; o >>= 1) ssum += __shfl_xor_sync(0xffffffffu, ssum, o);
    const float lse = mx + __logf(ssum);
    out2[(size_t)row * 64 + lane]      = v0 - lse;
    out2[(size_t)row * 64 + lane + 32] = v1 - lse;
}

// ------------------------- host -------------------------
extern "C" void kernel_launch(void* const* d_in, const int* in_sizes, int n_in,
                              void* d_out, int out_size)
{
    const float* feature = (const float*)d_in[0];
    const float* adj     = (const float*)d_in[1];
    const float* W1      = (const float*)d_in[2];
    const float* b1      = (const float*)d_in[3];
    const float* W2      = (const float*)d_in[4];
    const float* b2      = (const float*)d_in[5];

    const int hid  = in_sizes[3];              // 256
    const int fin  = in_sizes[2] / hid;        // 512
    const int n    = in_sizes[0] / fin;        // 10000

    // smem: STAGE*2; STAGE = 2*BM*80 + (PASSES-1)*BN*80
    constexpr int SM_G1 = 2 * (2 * 128 * 80 + 2 * 128 * 80);  // 81920 (3-pass, BN=128)
    constexpr int SM_G2 = 2 * (2 * 128 * 80 + 1 * 256 * 80);  // 81920 (2-pass, BN=256)
    constexpr int SM_G3 = 2 * (2 * 128 * 80 + 2 * 64  * 80);  // 61440 (3-pass, BN=64)
    constexpr int SM_G4 = 2 * (2 * 128 * 80 + 1 * 64  * 80);  // 51200 (2-pass, BN=64)
    cudaFuncSetAttribute((const void*)gemm_hmma<128,128,4,2,1,3>, cudaFuncAttributeMaxDynamicSharedMemorySize, SM_G1);
    cudaFuncSetAttribute((const void*)gemm_hmma<128,256,2,4,0,2>, cudaFuncAttributeMaxDynamicSharedMemorySize, SM_G2);
    cudaFuncSetAttribute((const void*)gemm_hmma<128,64,4,2,1,3>,  cudaFuncAttributeMaxDynamicSharedMemorySize, SM_G3);
    cudaFuncSetAttribute((const void*)gemm_hmma<128,64,4,2,0,2>,  cudaFuncAttributeMaxDynamicSharedMemorySize, SM_G4);

    __half *w1h, *w1l, *w2h, *w2l, *s1t, *s2t;
    float *p1, *p2;
    cudaGetSymbolAddress((void**)&w1h, g_W1T_hi); cudaGetSymbolAddress((void**)&w1l, g_W1T_lo);
    cudaGetSymbolAddress((void**)&w2h, g_W2T_hi); cudaGetSymbolAddress((void**)&w2l, g_W2T_lo);
    cudaGetSymbolAddress((void**)&s1t, g_S1T);    cudaGetSymbolAddress((void**)&s2t, g_S2T);
    cudaGetSymbolAddress((void**)&p1, g_P1);      cudaGetSymbolAddress((void**)&p2, g_P2);

    float* x1   = (float*)d_out;               // [n, 256]
    float* out2 = x1 + (size_t)n * hid;        // [n, 64]
    const int mb = (n + 127) / 128;            // 79

    // 0) weights -> transposed fp16 hi/lo
    prep_weights<<<512, 256>>>(W1, W2);
    // 1) S1T = (feature @ W1)^T  (3-pass: A=feature pair, B=W1T pair; out single fp16)
    gemm_hmma<128,128,4,2,1,3><<<dim3(mb, 2, 1), 256, SM_G1>>>(
        feature, fin, 1.0f, w1h, w1l, fin, n, fin, hid, nullptr, s1t);
    // 2) P1[s] = (adj*2^14) @ S1 partials (2-pass: A=adj pair scaled, B=S1T single; split-K x7)
    gemm_hmma<128,256,2,4,0,2><<<dim3(mb, 1, 7), 256, SM_G2>>>(
        adj, n, ADJ_SCALE, s1t, nullptr, n, n, n, hid, p1, nullptr);
    // 3) x1 = relu(2^-14 * sum P1 + b1) -> d_out
    reduce1<<<(n * 64 + 255) / 256, 256>>>(b1, x1, n, 7);
    // 4) S2T = (x1 @ W2)^T  (3-pass)
    gemm_hmma<128,64,4,2,1,3><<<dim3(mb, 1, 1), 256, SM_G3>>>(
        x1, hid, 1.0f, w2h, w2l, hid, n, hid, 64, nullptr, s2t);
    // 5) P2[s] = (adj*2^14) @ S2 partials (2-pass; split-K x4)
    gemm_hmma<128,64,4,2,0,2><<<dim3(mb, 1, 4), 256, SM_G4>>>(
        adj, n, ADJ_SCALE, s2t, nullptr, n, n, n, 64, p2, nullptr);
    // 6) out2 = log_softmax(2^-14 * sum P2 + b2) -> d_out
    reduce2<<<(n + 3) / 4, 128>>>(b2, out2, n, 4);
}

// round 11
// speedup vs baseline: 2.8967x; 1.1898x over previous
#include <cuda_runtime.h>
#include <cuda_fp16.h>
#include <cstdint>

#define DEV_INLINE __device__ __forceinline__

// ------------------------- global scratch (no allocs allowed) -------------------------
__device__ __half g_W1T_hi[256 * 512],  g_W1T_lo[256 * 512];
__device__ __half g_W2T_hi[64 * 256],   g_W2T_lo[64 * 256];
__device__ __half g_S1T[256 * 10000];         // S1^T single fp16
__device__ __half g_S2T[64 * 10000];          // S2^T single fp16
__device__ float  g_P1[8 * 10000 * 256];      // GEMM2 split-K partials [s][m][n] (scaled 2^14)
__device__ float  g_P2[4 * 10000 * 64];       // GEMM4 split-K partials [s][m][n] (scaled 2^14)

#define ADJ_SCALE 16384.0f
#define ADJ_INV   (1.0f / 16384.0f)

// ------------------------- helpers -------------------------
DEV_INLINE uint32_t smem_u32(const void* p) { return (uint32_t)__cvta_generic_to_shared(p); }

DEV_INLINE void cp_async16(uint32_t dst, const void* src, int bytes) {
    asm volatile("cp.async.cg.shared.global [%0], [%1], 16, %2;\n"
                 :: "r"(dst), "l"(src), "r"(bytes));
}
DEV_INLINE void cp_commit()  { asm volatile("cp.async.commit_group;\n" ::); }
DEV_INLINE void cp_wait_all(){ asm volatile("cp.async.wait_group 0;\n" ::); }

// fp32 pair -> packed fp16 (scaled), plus optional residual pair.
DEV_INLINE uint32_t pack2h(float x0, float x1, float s) {
    const __half2 h = __floats2half2_rn(x0 * s, x1 * s);
    return *(const uint32_t*)&h;
}
DEV_INLINE void split2h(float x0, float x1, float s, uint32_t& hh, uint32_t& ll) {
    const float y0 = x0 * s, y1 = x1 * s;
    const __half2 h = __floats2half2_rn(y0, y1);
    const float2 hf = __half22float2(h);
    const __half2 l = __floats2half2_rn(y0 - hf.x, y1 - hf.y);
    hh = *(const uint32_t*)&h;
    ll = *(const uint32_t*)&l;
}

DEV_INLINE void mma_f16(float* c, const uint32_t* a, const uint32_t* b) {
    asm volatile(
        "mma.sync.aligned.m16n8k16.row.col.f32.f16.f16.f32 "
        "{%0,%1,%2,%3}, {%4,%5,%6,%7}, {%8,%9}, {%0,%1,%2,%3};\n"
        : "+f"(c[0]), "+f"(c[1]), "+f"(c[2]), "+f"(c[3])
        : "r"(a[0]), "r"(a[1]), "r"(a[2]), "r"(a[3]), "r"(b[0]), "r"(b[1]));
}

DEV_INLINE void ldsm4(uint32_t addr, uint32_t& r0, uint32_t& r1, uint32_t& r2, uint32_t& r3) {
    asm volatile("ldmatrix.sync.aligned.m8n8.x4.shared.b16 {%0,%1,%2,%3}, [%4];"
                 : "=r"(r0), "=r"(r1), "=r"(r2), "=r"(r3) : "r"(addr));
}

// ------------------------- unified HMMA GEMM (fp16) -------------------------
// D[m,n] = sum_k (A[m,k]*scale) * BT[n,k].  BT fp16 K-major [N][K].
//   PASSES==1: A single, B single;  acc = A*B          (two fp16 trunc sources)
//   PASSES==2: A hi/lo,  B single;  acc = Ah*B + Al*B  (B trunc only)
//   PASSES==3: A hi/lo,  B hi/lo;   acc = Ah*Bh + Ah*Bl + Al*Bh (~2^-21)
// grid: (mBlocks, nBlocks, kSlices).
// EPI 0: P[slice][m][Ntot] fp32.  EPI 1: C[n][m] single fp16 (transposed, ld = M).
template <int BM, int BN, int WARPS_M, int WARPS_N, int EPI, int PASSES>
__global__ void __launch_bounds__(WARPS_M * WARPS_N * 32, 1)
gemm_hmma(const float* __restrict__ A, int lda, float scale,
          const __half* __restrict__ Bhi, const __half* __restrict__ Blo, int ldb,
          int M, int K, int Ntot,
          float* __restrict__ P, __half* __restrict__ C)
{
    constexpr int BK = 32;
    constexpr int THREADS = WARPS_M * WARPS_N * 32;
    constexpr int WM = BM / WARPS_M;
    constexpr int WN = BN / WARPS_N;
    constexpr int MT = WM / 16;
    constexpr int NT = WN / 8;
    constexpr int ROWB = 80;               // (BK+8)*2B rows: starts hit banks 0,20,8,28,... conflict-free
    constexpr int AV = (PASSES >= 2) ? 2 : 1;   // A variants in smem
    constexpr int BV = (PASSES == 3) ? 2 : 1;   // B variants in smem
    constexpr int AB   = BM * ROWB;
    constexpr int BB   = BN * ROWB;
    constexpr int OFF_ALO = AB;
    constexpr int OFF_BHI = AV * AB;
    constexpr int STAGE = AV * AB + BV * BB;
    constexpr int NF4 = (BM * BK / 4) / THREADS;   // float4 A loads per thread
    constexpr int NBC = (BN * 4) / THREADS;        // B cp.async chunks per thread (per variant)

    extern __shared__ char sm[];
    const uint32_t smb = smem_u32(sm);

    const int tid  = threadIdx.x;
    const int warp = tid >> 5;
    const int lane = tid & 31;
    const int wm = warp / WARPS_N;
    const int wn = warp % WARPS_N;
    const int g  = lane >> 2;
    const int tg = lane & 3;

    // ldmatrix per-lane quad coordinates
    const int aq_m = (lane & 7) + ((lane >> 3) & 1) * 8;
    const int aq_k = ((lane >> 4) & 1) * 8;
    const int bq_n = (lane & 7) + ((lane >> 4) & 1) * 8;
    const int bq_k = ((lane >> 3) & 1) * 8;

    const int m0 = blockIdx.x * BM;
    const int n0 = blockIdx.y * BN;
    Bhi += (size_t)n0 * ldb;
    if (PASSES == 3) Blo += (size_t)n0 * ldb;

    const int KS = gridDim.z, sl = blockIdx.z;
    const int nChTot = (K + BK - 1) / BK;
    const int cs = sl * nChTot / KS;
    const int ce = (sl + 1) * nChTot / KS;
    const int kB = cs * BK;
    const int kE = min(ce * BK, K);
    const int nCh = ce - cs;
    if (EPI == 0) P += (size_t)sl * M * Ntot;

    float acc[MT][NT][4];
    #pragma unroll
    for (int i = 0; i < MT; i++)
        #pragma unroll
        for (int j = 0; j < NT; j++)
            #pragma unroll
            for (int r = 0; r < 4; r++) acc[i][j][r] = 0.0f;

    float4 aReg[NF4];

    auto ldA = [&](int c) {
        const int k0 = kB + c * BK;
        #pragma unroll
        for (int i = 0; i < NF4; i++) {
            const int u = tid + i * THREADS;
            const int r = u >> 3, c4 = u & 7;
            const int mg = m0 + r, kg = k0 + c4 * 4;
            aReg[i] = (mg < M && kg < kE) ? *(const float4*)(A + (size_t)mg * lda + kg)
                                          : make_float4(0.f, 0.f, 0.f, 0.f);
        }
    };
    auto stA = [&](int s) {
        char* base = sm + s * STAGE;
        #pragma unroll
        for (int i = 0; i < NF4; i++) {
            const int u = tid + i * THREADS;
            const int r = u >> 3, c4 = u & 7;
            const int off = r * ROWB + c4 * 8;
            if (PASSES == 1) {
                const uint32_t h0 = pack2h(aReg[i].x, aReg[i].y, scale);
                const uint32_t h1 = pack2h(aReg[i].z, aReg[i].w, scale);
                *(uint2*)(base + off) = make_uint2(h0, h1);
            } else {
                uint32_t h0, l0, h1, l1;
                split2h(aReg[i].x, aReg[i].y, scale, h0, l0);
                split2h(aReg[i].z, aReg[i].w, scale, h1, l1);
                *(uint2*)(base + off)            = make_uint2(h0, h1);
                *(uint2*)(base + OFF_ALO + off)  = make_uint2(l0, l1);
            }
        }
    };
    auto ldB = [&](int c, int s) {
        const int k0 = kB + c * BK;
        #pragma unroll
        for (int i = 0; i < NBC; i++) {
            const int u = tid + i * THREADS;
            const int n = u >> 2, seg = u & 3;
            const int kk = k0 + seg * 8;
            const int by = (kk + 8 <= kE) ? 16 : 0;
            const uint32_t dst = smb + s * STAGE + OFF_BHI + n * ROWB + seg * 16;
            cp_async16(dst, Bhi + (size_t)n * ldb + kk, by);
            if (PASSES == 3)
                cp_async16(dst + BB, Blo + (size_t)n * ldb + kk, by);
        }
        cp_commit();
    };

    // prologue: stage 0
    ldA(0);
    ldB(0, 0);
    cp_wait_all();
    stA(0);
    __syncthreads();

    for (int c = 0; c < nCh; c++) {
        const int s = c & 1;
        if (c + 1 < nCh) { ldA(c + 1); ldB(c + 1, s ^ 1); }

        const uint32_t base = smb + s * STAGE;
        #pragma unroll
        for (int kk = 0; kk < BK; kk += 16) {
            uint32_t ah[MT][4], al[MT][4];
            const uint32_t aAddr = base + (wm * WM + aq_m) * ROWB + (kk + aq_k) * 2;
            #pragma unroll
            for (int mt = 0; mt < MT; mt++) {
                ldsm4(aAddr + mt * 16 * ROWB, ah[mt][0], ah[mt][1], ah[mt][2], ah[mt][3]);
                if (PASSES >= 2)
                    ldsm4(aAddr + mt * 16 * ROWB + OFF_ALO, al[mt][0], al[mt][1], al[mt][2], al[mt][3]);
            }
            const uint32_t bAddr = base + OFF_BHI + (wn * WN + bq_n) * ROWB + (kk + bq_k) * 2;
            #pragma unroll
            for (int p = 0; p < NT / 2; p++) {
                uint32_t bh[4];
                ldsm4(bAddr + p * 16 * ROWB, bh[0], bh[1], bh[2], bh[3]);
                if (PASSES == 3) {
                    uint32_t bl[4];
                    ldsm4(bAddr + p * 16 * ROWB + BB, bl[0], bl[1], bl[2], bl[3]);
                    #pragma unroll
                    for (int h = 0; h < 2; h++) {
                        const int nt = 2 * p + h;
                        #pragma unroll
                        for (int mt = 0; mt < MT; mt++) {
                            mma_f16(acc[mt][nt], ah[mt], bh + 2 * h);
                            mma_f16(acc[mt][nt], ah[mt], bl + 2 * h);
                            mma_f16(acc[mt][nt], al[mt], bh + 2 * h);
                        }
                    }
                } else if (PASSES == 2) {
                    #pragma unroll
                    for (int h = 0; h < 2; h++) {
                        const int nt = 2 * p + h;
                        #pragma unroll
                        for (int mt = 0; mt < MT; mt++) {
                            mma_f16(acc[mt][nt], ah[mt], bh + 2 * h);
                            mma_f16(acc[mt][nt], al[mt], bh + 2 * h);
                        }
                    }
                } else {
                    #pragma unroll
                    for (int h = 0; h < 2; h++) {
                        const int nt = 2 * p + h;
                        #pragma unroll
                        for (int mt = 0; mt < MT; mt++)
                            mma_f16(acc[mt][nt], ah[mt], bh + 2 * h);
                    }
                }
            }
        }

        if (c + 1 < nCh) { cp_wait_all(); stA(s ^ 1); }
        __syncthreads();
    }

    // ------------- epilogue -------------
    #pragma unroll
    for (int mt = 0; mt < MT; mt++) {
        const int r0 = m0 + wm * WM + mt * 16 + g;
        const int r1 = r0 + 8;
        #pragma unroll
        for (int nt = 0; nt < NT; nt++) {
            const int col = n0 + wn * WN + nt * 8 + 2 * tg;
            if (EPI == 0) {
                if (r0 < M) *(float2*)(P + (size_t)r0 * Ntot + col) = make_float2(acc[mt][nt][0], acc[mt][nt][1]);
                if (r1 < M) *(float2*)(P + (size_t)r1 * Ntot + col) = make_float2(acc[mt][nt][2], acc[mt][nt][3]);
            } else {
                if (r0 < M) {
                    C[(size_t)col * M + r0]       = __float2half(acc[mt][nt][0]);
                    C[(size_t)(col + 1) * M + r0] = __float2half(acc[mt][nt][1]);
                }
                if (r1 < M) {
                    C[(size_t)col * M + r1]       = __float2half(acc[mt][nt][2]);
                    C[(size_t)(col + 1) * M + r1] = __float2half(acc[mt][nt][3]);
                }
            }
        }
    }
}

// ------------------------- prep: W1/W2 -> transposed fp16 hi/lo -------------------------
__global__ void prep_weights(const float* __restrict__ W1, const float* __restrict__ W2)
{
    const int i = blockIdx.x * blockDim.x + threadIdx.x;
    if (i < 512 * 256) {
        const int k = i / 256, n = i % 256;
        const float v = W1[i];
        const __half h = __float2half_rn(v);
        g_W1T_hi[n * 512 + k] = h;
        g_W1T_lo[n * 512 + k] = __float2half_rn(v - __half2float(h));
    }
    if (i < 256 * 64) {
        const int k = i / 64, n = i % 64;
        const float v = W2[i];
        const __half h = __float2half_rn(v);
        g_W2T_hi[n * 256 + k] = h;
        g_W2T_lo[n * 256 + k] = __float2half_rn(v - __half2float(h));
    }
}

// ------------------------- reduce1: x1 = relu(inv*sum_s P1 + b1) -------------------------
__global__ void reduce1(const float* __restrict__ b1, float* __restrict__ x1, int M, int KS)
{
    const int i = blockIdx.x * blockDim.x + threadIdx.x;   // float4 index
    const int tot = M * 64;                                // M*256/4
    if (i >= tot) return;
    const float4* P = (const float4*)g_P1;
    float4 v = P[i];
    for (int s = 1; s < KS; s++) {
        const float4 w = P[(size_t)s * tot + i];
        v.x += w.x; v.y += w.y; v.z += w.z; v.w += w.w;
    }
    const float4 b = ((const float4*)b1)[i & 63];
    v.x = fmaxf(v.x * ADJ_INV + b.x, 0.f); v.y = fmaxf(v.y * ADJ_INV + b.y, 0.f);
    v.z = fmaxf(v.z * ADJ_INV + b.z, 0.f); v.w = fmaxf(v.w * ADJ_INV + b.w, 0.f);
    ((float4*)x1)[i] = v;
}

// ------------------------- reduce2: out2 = log_softmax(inv*sum_s P2 + b2) -------------------------
__global__ void reduce2(const float* __restrict__ b2, float* __restrict__ out2, int M, int KS)
{
    const int row = blockIdx.x * (blockDim.x >> 5) + (threadIdx.x >> 5);
    if (row >= M) return;
    const int lane = threadIdx.x & 31;
    const size_t tot = (size_t)M * 64;
    float v0 = 0.f, v1 = 0.f;
    for (int s = 0; s < KS; s++) {
        v0 += g_P2[s * tot + (size_t)row * 64 + lane];
        v1 += g_P2[s * tot + (size_t)row * 64 + lane + 32];
    }
    v0 = v0 * ADJ_INV + b2[lane];
    v1 = v1 * ADJ_INV + b2[lane + 32];
    float mx = fmaxf(v0, v1);
    #pragma unroll
    for (int o = 16; o > 0; o >>= 1) mx = fmaxf(mx, __shfl_xor_sync(0xffffffffu, mx, o));
    float ssum = __expf(v0 - mx) + __expf(v1 - mx);
    #pragma unroll
    for (int o = 16; o > 0; o >>= 1) ssum += __shfl_xor_sync(0xffffffffu, ssum, o);
    const float lse = mx + __logf(ssum);
    out2[(size_t)row * 64 + lane]      = v0 - lse;
    out2[(size_t)row * 64 + lane + 32] = v1 - lse;
}

// ------------------------- host -------------------------
extern "C" void kernel_launch(void* const* d_in, const int* in_sizes, int n_in,
                              void* d_out, int out_size)
{
    const float* feature = (const float*)d_in[0];
    const float* adj     = (const float*)d_in[1];
    const float* W1      = (const float*)d_in[2];
    const float* b1      = (const float*)d_in[3];
    const float* W2      = (const float*)d_in[4];
    const float* b2      = (const float*)d_in[5];

    const int hid  = in_sizes[3];              // 256
    const int fin  = in_sizes[2] / hid;        // 512
    const int n    = in_sizes[0] / fin;        // 10000

    // smem: 2 stages; STAGE = AV*BM*80 + BV*BN*80
    constexpr int SM_G1 = 2 * (2 * 128 * 80 + 2 * 128 * 80);  // 81920 (3-pass, BN=128)
    constexpr int SM_G2 = 2 * (1 * 128 * 80 + 1 * 256 * 80);  // 61440 (1-pass, BN=256)
    constexpr int SM_G3 = 2 * (2 * 128 * 80 + 2 * 64  * 80);  // 61440 (3-pass, BN=64)
    constexpr int SM_G4 = 2 * (1 * 128 * 80 + 1 * 64  * 80);  // 30720 (1-pass, BN=64)
    cudaFuncSetAttribute((const void*)gemm_hmma<128,128,4,2,1,3>, cudaFuncAttributeMaxDynamicSharedMemorySize, SM_G1);
    cudaFuncSetAttribute((const void*)gemm_hmma<128,256,2,4,0,1>, cudaFuncAttributeMaxDynamicSharedMemorySize, SM_G2);
    cudaFuncSetAttribute((const void*)gemm_hmma<128,64,4,2,1,3>,  cudaFuncAttributeMaxDynamicSharedMemorySize, SM_G3);
    cudaFuncSetAttribute((const void*)gemm_hmma<128,64,4,2,0,1>,  cudaFuncAttributeMaxDynamicSharedMemorySize, SM_G4);

    __half *w1h, *w1l, *w2h, *w2l, *s1t, *s2t;
    float *p1, *p2;
    cudaGetSymbolAddress((void**)&w1h, g_W1T_hi); cudaGetSymbolAddress((void**)&w1l, g_W1T_lo);
    cudaGetSymbolAddress((void**)&w2h, g_W2T_hi); cudaGetSymbolAddress((void**)&w2l, g_W2T_lo);
    cudaGetSymbolAddress((void**)&s1t, g_S1T);    cudaGetSymbolAddress((void**)&s2t, g_S2T);
    cudaGetSymbolAddress((void**)&p1, g_P1);      cudaGetSymbolAddress((void**)&p2, g_P2);

    float* x1   = (float*)d_out;               // [n, 256]
    float* out2 = x1 + (size_t)n * hid;        // [n, 64]
    const int mb = (n + 127) / 128;            // 79

    // 0) weights -> transposed fp16 hi/lo
    prep_weights<<<512, 256>>>(W1, W2);
    // 1) S1T = (feature @ W1)^T  (3-pass, near-fp32; out single fp16)
    gemm_hmma<128,128,4,2,1,3><<<dim3(mb, 2, 1), 256, SM_G1>>>(
        feature, fin, 1.0f, w1h, w1l, fin, n, fin, hid, nullptr, s1t);
    // 2) P1[s] = (adj*2^14) @ S1 partials (1-pass: both sides single fp16; split-K x7)
    gemm_hmma<128,256,2,4,0,1><<<dim3(mb, 1, 7), 256, SM_G2>>>(
        adj, n, ADJ_SCALE, s1t, nullptr, n, n, n, hid, p1, nullptr);
    // 3) x1 = relu(2^-14 * sum P1 + b1) -> d_out
    reduce1<<<(n * 64 + 255) / 256, 256>>>(b1, x1, n, 7);
    // 4) S2T = (x1 @ W2)^T  (3-pass)
    gemm_hmma<128,64,4,2,1,3><<<dim3(mb, 1, 1), 256, SM_G3>>>(
        x1, hid, 1.0f, w2h, w2l, hid, n, hid, 64, nullptr, s2t);
    // 5) P2[s] = (adj*2^14) @ S2 partials (1-pass; split-K x4)
    gemm_hmma<128,64,4,2,0,1><<<dim3(mb, 1, 4), 256, SM_G4>>>(
        adj, n, ADJ_SCALE, s2t, nullptr, n, n, n, 64, p2, nullptr);
    // 6) out2 = log_softmax(2^-14 * sum P2 + b2) -> d_out
    reduce2<<<(n + 3) / 4, 128>>>(b2, out2, n, 4);
}

// round 12
// speedup vs baseline: 3.3190x; 1.1458x over previous
#include <cuda_runtime.h>
#include <cuda_fp16.h>
#include <cstdint>

#define DEV_INLINE __device__ __forceinline__

// ------------------------- global scratch (no allocs allowed) -------------------------
__device__ __half g_adj16[100000000];         // adj * 2^14 as fp16 (200 MB)
__device__ __half g_W1T_hi[256 * 512],  g_W1T_lo[256 * 512];
__device__ __half g_W2T_hi[64 * 256],   g_W2T_lo[64 * 256];
__device__ __half g_S1T[256 * 10000];         // S1^T single fp16
__device__ __half g_S2T[64 * 10000];          // S2^T single fp16
__device__ float  g_P1[8 * 10000 * 256];      // GEMM2 split-K partials [s][m][n] (scaled 2^14)
__device__ float  g_P2[4 * 10000 * 64];       // GEMM4 split-K partials [s][m][n] (scaled 2^14)

#define ADJ_SCALE 16384.0f
#define ADJ_INV   (1.0f / 16384.0f)

// ------------------------- helpers -------------------------
DEV_INLINE uint32_t smem_u32(const void* p) { return (uint32_t)__cvta_generic_to_shared(p); }

DEV_INLINE void cp_async16(uint32_t dst, const void* src, int bytes) {
    asm volatile("cp.async.cg.shared.global [%0], [%1], 16, %2;\n"
                 :: "r"(dst), "l"(src), "r"(bytes));
}
DEV_INLINE void cp_commit()  { asm volatile("cp.async.commit_group;\n" ::); }
DEV_INLINE void cp_wait_all(){ asm volatile("cp.async.wait_group 0;\n" ::); }

DEV_INLINE void split2h(float x0, float x1, float s, uint32_t& hh, uint32_t& ll) {
    const float y0 = x0 * s, y1 = x1 * s;
    const __half2 h = __floats2half2_rn(y0, y1);
    const float2 hf = __half22float2(h);
    const __half2 l = __floats2half2_rn(y0 - hf.x, y1 - hf.y);
    hh = *(const uint32_t*)&h;
    ll = *(const uint32_t*)&l;
}

DEV_INLINE void mma_f16(float* c, const uint32_t* a, const uint32_t* b) {
    asm volatile(
        "mma.sync.aligned.m16n8k16.row.col.f32.f16.f16.f32 "
        "{%0,%1,%2,%3}, {%4,%5,%6,%7}, {%8,%9}, {%0,%1,%2,%3};\n"
        : "+f"(c[0]), "+f"(c[1]), "+f"(c[2]), "+f"(c[3])
        : "r"(a[0]), "r"(a[1]), "r"(a[2]), "r"(a[3]), "r"(b[0]), "r"(b[1]));
}

DEV_INLINE void ldsm4(uint32_t addr, uint32_t& r0, uint32_t& r1, uint32_t& r2, uint32_t& r3) {
    asm volatile("ldmatrix.sync.aligned.m8n8.x4.shared.b16 {%0,%1,%2,%3}, [%4];"
                 : "=r"(r0), "=r"(r1), "=r"(r2), "=r"(r3) : "r"(addr));
}

// ------------------------- gemm16: both operands fp16, 1 MMA pass -------------------------
// D[m,n] = sum_k A16[m,k] * BT[n,k].  A16 [M][lda], BT [N][ldb], both K-major fp16.
// All loads via cp.async (no in-loop conversion).  BKT=64 chunks.
// Output: P[slice][m][Ntot] fp32 partials.  grid (mBlocks, 1, kSlices).
template <int BM, int BN, int WARPS_M, int WARPS_N, int BKT>
__global__ void __launch_bounds__(WARPS_M * WARPS_N * 32)
gemm16(const __half* __restrict__ A, int lda,
       const __half* __restrict__ B, int ldb,
       int M, int K, int Ntot, float* __restrict__ P)
{
    constexpr int THREADS = WARPS_M * WARPS_N * 32;
    constexpr int WM = BM / WARPS_M;
    constexpr int WN = BN / WARPS_N;
    constexpr int MT = WM / 16;
    constexpr int NT = WN / 8;
    constexpr int ROWB = (BKT + 8) * 2;     // 144 for BKT=64: rows start at banks 0,4,8,... conflict-free
    constexpr int AB = BM * ROWB;
    constexpr int BB = BN * ROWB;
    constexpr int OFF_B = AB;
    constexpr int STAGE = AB + BB;
    constexpr int SEG = BKT / 8;            // 16B segments per row
    constexpr int NAC = BM * SEG / THREADS;
    constexpr int NBC = BN * SEG / THREADS;

    extern __shared__ char sm[];
    const uint32_t smb = smem_u32(sm);

    const int tid  = threadIdx.x;
    const int warp = tid >> 5;
    const int lane = tid & 31;
    const int wm = warp / WARPS_N;
    const int wn = warp % WARPS_N;
    const int g  = lane >> 2;
    const int tg = lane & 3;

    const int aq_m = (lane & 7) + ((lane >> 3) & 1) * 8;
    const int aq_k = ((lane >> 4) & 1) * 8;
    const int bq_n = (lane & 7) + ((lane >> 4) & 1) * 8;
    const int bq_k = ((lane >> 3) & 1) * 8;

    const int m0 = blockIdx.x * BM;

    const int KS = gridDim.z, sl = blockIdx.z;
    const int nChTot = (K + BKT - 1) / BKT;
    const int cs = sl * nChTot / KS;
    const int ce = (sl + 1) * nChTot / KS;
    const int kB = cs * BKT;
    const int kE = min(ce * BKT, K);
    const int nCh = ce - cs;
    P += (size_t)sl * M * Ntot;

    float acc[MT][NT][4];
    #pragma unroll
    for (int i = 0; i < MT; i++)
        #pragma unroll
        for (int j = 0; j < NT; j++)
            #pragma unroll
            for (int r = 0; r < 4; r++) acc[i][j][r] = 0.0f;

    auto ld = [&](int c, int s) {
        const int k0 = kB + c * BKT;
        #pragma unroll
        for (int i = 0; i < NAC; i++) {
            const int u = tid + i * THREADS;
            const int r = u / SEG, seg = u % SEG;
            const int kk = k0 + seg * 8;
            const int mg = m0 + r;
            const int by = (mg < M && kk + 8 <= kE) ? 16 : 0;
            const int mc = (mg < M) ? mg : (M - 1);
            cp_async16(smb + s * STAGE + r * ROWB + seg * 16,
                       A + (size_t)mc * lda + kk, by);
        }
        #pragma unroll
        for (int i = 0; i < NBC; i++) {
            const int u = tid + i * THREADS;
            const int r = u / SEG, seg = u % SEG;
            const int kk = k0 + seg * 8;
            const int by = (kk + 8 <= kE) ? 16 : 0;
            cp_async16(smb + s * STAGE + OFF_B + r * ROWB + seg * 16,
                       B + (size_t)r * ldb + kk, by);
        }
        cp_commit();
    };

    // prologue
    ld(0, 0);
    cp_wait_all();
    __syncthreads();

    for (int c = 0; c < nCh; c++) {
        const int s = c & 1;
        if (c + 1 < nCh) ld(c + 1, s ^ 1);

        const uint32_t base = smb + s * STAGE;
        #pragma unroll
        for (int kk = 0; kk < BKT; kk += 16) {
            uint32_t ah[MT][4];
            const uint32_t aAddr = base + (wm * WM + aq_m) * ROWB + (kk + aq_k) * 2;
            #pragma unroll
            for (int mt = 0; mt < MT; mt++)
                ldsm4(aAddr + mt * 16 * ROWB, ah[mt][0], ah[mt][1], ah[mt][2], ah[mt][3]);
            const uint32_t bAddr = base + OFF_B + (wn * WN + bq_n) * ROWB + (kk + bq_k) * 2;
            #pragma unroll
            for (int p = 0; p < NT / 2; p++) {
                uint32_t bh[4];
                ldsm4(bAddr + p * 16 * ROWB, bh[0], bh[1], bh[2], bh[3]);
                #pragma unroll
                for (int h = 0; h < 2; h++) {
                    const int nt = 2 * p + h;
                    #pragma unroll
                    for (int mt = 0; mt < MT; mt++)
                        mma_f16(acc[mt][nt], ah[mt], bh + 2 * h);
                }
            }
        }

        if (c + 1 < nCh) cp_wait_all();
        __syncthreads();
    }

    // epilogue: fp32 partials
    #pragma unroll
    for (int mt = 0; mt < MT; mt++) {
        const int r0 = m0 + wm * WM + mt * 16 + g;
        const int r1 = r0 + 8;
        #pragma unroll
        for (int nt = 0; nt < NT; nt++) {
            const int col = wn * WN + nt * 8 + 2 * tg;
            if (r0 < M) *(float2*)(P + (size_t)r0 * Ntot + col) = make_float2(acc[mt][nt][0], acc[mt][nt][1]);
            if (r1 < M) *(float2*)(P + (size_t)r1 * Ntot + col) = make_float2(acc[mt][nt][2], acc[mt][nt][3]);
        }
    }
}

// ------------------------- gemm_hmma: fp32 A (3-pass hi/lo), for G1/G3 -------------------------
// EPI 1: C[n][m] single fp16 (transposed, ld = M).
template <int BM, int BN, int WARPS_M, int WARPS_N, int PASSES>
__global__ void __launch_bounds__(WARPS_M * WARPS_N * 32)
gemm_hmma(const float* __restrict__ A, int lda,
          const __half* __restrict__ Bhi, const __half* __restrict__ Blo, int ldb,
          int M, int K, int Ntot, __half* __restrict__ C)
{
    constexpr int BK = 32;
    constexpr int THREADS = WARPS_M * WARPS_N * 32;
    constexpr int WM = BM / WARPS_M;
    constexpr int WN = BN / WARPS_N;
    constexpr int MT = WM / 16;
    constexpr int NT = WN / 8;
    constexpr int ROWB = 80;
    constexpr int AB   = BM * ROWB;
    constexpr int BB   = BN * ROWB;
    constexpr int OFF_ALO = AB;
    constexpr int OFF_BHI = 2 * AB;
    constexpr int STAGE = 2 * AB + 2 * BB;
    constexpr int NF4 = (BM * BK / 4) / THREADS;
    constexpr int NBC = (BN * 4) / THREADS;

    extern __shared__ char sm[];
    const uint32_t smb = smem_u32(sm);

    const int tid  = threadIdx.x;
    const int warp = tid >> 5;
    const int lane = tid & 31;
    const int wm = warp / WARPS_N;
    const int wn = warp % WARPS_N;
    const int g  = lane >> 2;
    const int tg = lane & 3;

    const int aq_m = (lane & 7) + ((lane >> 3) & 1) * 8;
    const int aq_k = ((lane >> 4) & 1) * 8;
    const int bq_n = (lane & 7) + ((lane >> 4) & 1) * 8;
    const int bq_k = ((lane >> 3) & 1) * 8;

    const int m0 = blockIdx.x * BM;
    const int n0 = blockIdx.y * BN;
    Bhi += (size_t)n0 * ldb;
    Blo += (size_t)n0 * ldb;

    const int K0 = 0, KE = K;
    const int nCh = (K + BK - 1) / BK;

    float acc[MT][NT][4];
    #pragma unroll
    for (int i = 0; i < MT; i++)
        #pragma unroll
        for (int j = 0; j < NT; j++)
            #pragma unroll
            for (int r = 0; r < 4; r++) acc[i][j][r] = 0.0f;

    float4 aReg[NF4];

    auto ldA = [&](int c) {
        const int k0 = K0 + c * BK;
        #pragma unroll
        for (int i = 0; i < NF4; i++) {
            const int u = tid + i * THREADS;
            const int r = u >> 3, c4 = u & 7;
            const int mg = m0 + r, kg = k0 + c4 * 4;
            aReg[i] = (mg < M && kg < KE) ? *(const float4*)(A + (size_t)mg * lda + kg)
                                          : make_float4(0.f, 0.f, 0.f, 0.f);
        }
    };
    auto stA = [&](int s) {
        char* base = sm + s * STAGE;
        #pragma unroll
        for (int i = 0; i < NF4; i++) {
            const int u = tid + i * THREADS;
            const int r = u >> 3, c4 = u & 7;
            const int off = r * ROWB + c4 * 8;
            uint32_t h0, l0, h1, l1;
            split2h(aReg[i].x, aReg[i].y, 1.0f, h0, l0);
            split2h(aReg[i].z, aReg[i].w, 1.0f, h1, l1);
            *(uint2*)(base + off)            = make_uint2(h0, h1);
            *(uint2*)(base + OFF_ALO + off)  = make_uint2(l0, l1);
        }
    };
    auto ldB = [&](int c, int s) {
        const int k0 = K0 + c * BK;
        #pragma unroll
        for (int i = 0; i < NBC; i++) {
            const int u = tid + i * THREADS;
            const int n = u >> 2, seg = u & 3;
            const int kk = k0 + seg * 8;
            const int by = (kk + 8 <= KE) ? 16 : 0;
            const uint32_t dst = smb + s * STAGE + OFF_BHI + n * ROWB + seg * 16;
            cp_async16(dst, Bhi + (size_t)n * ldb + kk, by);
            cp_async16(dst + BB, Blo + (size_t)n * ldb + kk, by);
        }
        cp_commit();
    };

    ldA(0);
    ldB(0, 0);
    cp_wait_all();
    stA(0);
    __syncthreads();

    for (int c = 0; c < nCh; c++) {
        const int s = c & 1;
        if (c + 1 < nCh) { ldA(c + 1); ldB(c + 1, s ^ 1); }

        const uint32_t base = smb + s * STAGE;
        #pragma unroll
        for (int kk = 0; kk < BK; kk += 16) {
            uint32_t ah[MT][4], al[MT][4];
            const uint32_t aAddr = base + (wm * WM + aq_m) * ROWB + (kk + aq_k) * 2;
            #pragma unroll
            for (int mt = 0; mt < MT; mt++) {
                ldsm4(aAddr + mt * 16 * ROWB,           ah[mt][0], ah[mt][1], ah[mt][2], ah[mt][3]);
                ldsm4(aAddr + mt * 16 * ROWB + OFF_ALO, al[mt][0], al[mt][1], al[mt][2], al[mt][3]);
            }
            const uint32_t bAddr = base + OFF_BHI + (wn * WN + bq_n) * ROWB + (kk + bq_k) * 2;
            #pragma unroll
            for (int p = 0; p < NT / 2; p++) {
                uint32_t bh[4], bl[4];
                ldsm4(bAddr + p * 16 * ROWB,      bh[0], bh[1], bh[2], bh[3]);
                ldsm4(bAddr + p * 16 * ROWB + BB, bl[0], bl[1], bl[2], bl[3]);
                #pragma unroll
                for (int h = 0; h < 2; h++) {
                    const int nt = 2 * p + h;
                    #pragma unroll
                    for (int mt = 0; mt < MT; mt++) {
                        mma_f16(acc[mt][nt], ah[mt], bh + 2 * h);
                        mma_f16(acc[mt][nt], ah[mt], bl + 2 * h);
                        mma_f16(acc[mt][nt], al[mt], bh + 2 * h);
                    }
                }
            }
        }

        if (c + 1 < nCh) { cp_wait_all(); stA(s ^ 1); }
        __syncthreads();
    }

    // epilogue: single fp16 transposed
    #pragma unroll
    for (int mt = 0; mt < MT; mt++) {
        const int r0 = m0 + wm * WM + mt * 16 + g;
        const int r1 = r0 + 8;
        #pragma unroll
        for (int nt = 0; nt < NT; nt++) {
            const int col = n0 + wn * WN + nt * 8 + 2 * tg;
            if (r0 < M) {
                C[(size_t)col * M + r0]       = __float2half(acc[mt][nt][0]);
                C[(size_t)(col + 1) * M + r0] = __float2half(acc[mt][nt][1]);
            }
            if (r1 < M) {
                C[(size_t)col * M + r1]       = __float2half(acc[mt][nt][2]);
                C[(size_t)(col + 1) * M + r1] = __float2half(acc[mt][nt][3]);
            }
        }
    }
}

// ------------------------- prep: adj -> fp16 (scaled 2^14) -------------------------
__global__ void prep_adj(const float* __restrict__ adj, int total8)
{
    const int i = blockIdx.x * blockDim.x + threadIdx.x;
    if (i >= total8) return;
    const float4* s = (const float4*)adj + 2 * (size_t)i;
    const float4 a = s[0], b = s[1];
    const __half2 h0 = __floats2half2_rn(a.x * ADJ_SCALE, a.y * ADJ_SCALE);
    const __half2 h1 = __floats2half2_rn(a.z * ADJ_SCALE, a.w * ADJ_SCALE);
    const __half2 h2 = __floats2half2_rn(b.x * ADJ_SCALE, b.y * ADJ_SCALE);
    const __half2 h3 = __floats2half2_rn(b.z * ADJ_SCALE, b.w * ADJ_SCALE);
    uint4 v;
    v.x = *(const uint32_t*)&h0; v.y = *(const uint32_t*)&h1;
    v.z = *(const uint32_t*)&h2; v.w = *(const uint32_t*)&h3;
    ((uint4*)g_adj16)[i] = v;
}

// ------------------------- prep: W1/W2 -> transposed fp16 hi/lo -------------------------
__global__ void prep_weights(const float* __restrict__ W1, const float* __restrict__ W2)
{
    const int i = blockIdx.x * blockDim.x + threadIdx.x;
    if (i < 512 * 256) {
        const int k = i / 256, n = i % 256;
        const float v = W1[i];
        const __half h = __float2half_rn(v);
        g_W1T_hi[n * 512 + k] = h;
        g_W1T_lo[n * 512 + k] = __float2half_rn(v - __half2float(h));
    }
    if (i < 256 * 64) {
        const int k = i / 64, n = i % 64;
        const float v = W2[i];
        const __half h = __float2half_rn(v);
        g_W2T_hi[n * 256 + k] = h;
        g_W2T_lo[n * 256 + k] = __float2half_rn(v - __half2float(h));
    }
}

// ------------------------- reduce1: x1 = relu(inv*sum_s P1 + b1) -------------------------
__global__ void reduce1(const float* __restrict__ b1, float* __restrict__ x1, int M, int KS)
{
    const int i = blockIdx.x * blockDim.x + threadIdx.x;   // float4 index
    const int tot = M * 64;
    if (i >= tot) return;
    const float4* P = (const float4*)g_P1;
    float4 v = P[i];
    for (int s = 1; s < KS; s++) {
        const float4 w = P[(size_t)s * tot + i];
        v.x += w.x; v.y += w.y; v.z += w.z; v.w += w.w;
    }
    const float4 b = ((const float4*)b1)[i & 63];
    v.x = fmaxf(v.x * ADJ_INV + b.x, 0.f); v.y = fmaxf(v.y * ADJ_INV + b.y, 0.f);
    v.z = fmaxf(v.z * ADJ_INV + b.z, 0.f); v.w = fmaxf(v.w * ADJ_INV + b.w, 0.f);
    ((float4*)x1)[i] = v;
}

// ------------------------- reduce2: out2 = log_softmax(inv*sum_s P2 + b2) -------------------------
__global__ void reduce2(const float* __restrict__ b2, float* __restrict__ out2, int M, int KS)
{
    const int row = blockIdx.x * (blockDim.x >> 5) + (threadIdx.x >> 5);
    if (row >= M) return;
    const int lane = threadIdx.x & 31;
    const size_t tot = (size_t)M * 64;
    float v0 = 0.f, v1 = 0.f;
    for (int s = 0; s < KS; s++) {
        v0 += g_P2[s * tot + (size_t)row * 64 + lane];
        v1 += g_P2[s * tot + (size_t)row * 64 + lane + 32];
    }
    v0 = v0 * ADJ_INV + b2[lane];
    v1 = v1 * ADJ_INV + b2[lane + 32];
    float mx = fmaxf(v0, v1);
    #pragma unroll
    for (int o = 16; o > 0; o >>= 1) mx = fmaxf(mx, __shfl_xor_sync(0xffffffffu, mx, o));
    float ssum = __expf(v0 - mx) + __expf(v1 - mx);
    #pragma unroll
    for (int o = 16; o > 0; o >>= 1) ssum += __shfl_xor_sync(0xffffffffu, ssum, o);
    const float lse = mx + __logf(ssum);
    out2[(size_t)row * 64 + lane]      = v0 - lse;
    out2[(size_t)row * 64 + lane + 32] = v1 - lse;
}

// ------------------------- host -------------------------
extern "C" void kernel_launch(void* const* d_in, const int* in_sizes, int n_in,
                              void* d_out, int out_size)
{
    const float* feature = (const float*)d_in[0];
    const float* adj     = (const float*)d_in[1];
    const float* W1      = (const float*)d_in[2];
    const float* b1      = (const float*)d_in[3];
    const float* W2      = (const float*)d_in[4];
    const float* b2      = (const float*)d_in[5];

    const int hid  = in_sizes[3];              // 256
    const int fin  = in_sizes[2] / hid;        // 512
    const int n    = in_sizes[0] / fin;        // 10000

    // smem sizes
    constexpr int SM_G1 = 2 * (2 * 128 * 80 + 2 * 128 * 80);    //  81920 (3-pass, BN=128, BK=32)
    constexpr int SM_G2 = 2 * (128 * 144 + 256 * 144);          // 110592 (fp16x2, BN=256, BK=64)
    constexpr int SM_G3 = 2 * (2 * 128 * 80 + 2 * 64 * 80);     //  61440 (3-pass, BN=64, BK=32)
    constexpr int SM_G4 = 2 * (128 * 144 + 64 * 144);           //  55296 (fp16x2, BN=64, BK=64)
    cudaFuncSetAttribute((const void*)gemm_hmma<128,128,4,2,3>, cudaFuncAttributeMaxDynamicSharedMemorySize, SM_G1);
    cudaFuncSetAttribute((const void*)gemm16<128,256,2,4,64>,   cudaFuncAttributeMaxDynamicSharedMemorySize, SM_G2);
    cudaFuncSetAttribute((const void*)gemm_hmma<128,64,4,2,3>,  cudaFuncAttributeMaxDynamicSharedMemorySize, SM_G3);
    cudaFuncSetAttribute((const void*)gemm16<128,64,4,2,64>,    cudaFuncAttributeMaxDynamicSharedMemorySize, SM_G4);

    __half *adj16, *w1h, *w1l, *w2h, *w2l, *s1t, *s2t;
    float *p1, *p2;
    cudaGetSymbolAddress((void**)&adj16, g_adj16);
    cudaGetSymbolAddress((void**)&w1h, g_W1T_hi); cudaGetSymbolAddress((void**)&w1l, g_W1T_lo);
    cudaGetSymbolAddress((void**)&w2h, g_W2T_hi); cudaGetSymbolAddress((void**)&w2l, g_W2T_lo);
    cudaGetSymbolAddress((void**)&s1t, g_S1T);    cudaGetSymbolAddress((void**)&s2t, g_S2T);
    cudaGetSymbolAddress((void**)&p1, g_P1);      cudaGetSymbolAddress((void**)&p2, g_P2);

    float* x1   = (float*)d_out;               // [n, 256]
    float* out2 = x1 + (size_t)n * hid;        // [n, 64]
    const int mb = (n + 127) / 128;            // 79

    // 0) preps: weights -> fp16 hi/lo; adj -> fp16 (scaled)
    prep_weights<<<512, 256>>>(W1, W2);
    const int total8 = (n * n) / 8;            // 12.5M uint4 stores
    prep_adj<<<(total8 + 255) / 256, 256>>>(adj, total8);
    // 1) S1T = (feature @ W1)^T  (3-pass, near-fp32; out single fp16)
    gemm_hmma<128,128,4,2,3><<<dim3(mb, 2, 1), 256, SM_G1>>>(
        feature, fin, w1h, w1l, fin, n, fin, hid, s1t);
    // 2) P1[s] = adj16 @ S1 partials (both fp16, split-K x7)
    gemm16<128,256,2,4,64><<<dim3(mb, 1, 7), 256, SM_G2>>>(
        adj16, n, s1t, n, n, n, hid, p1);
    // 3) x1 = relu(2^-14 * sum P1 + b1) -> d_out
    reduce1<<<(n * 64 + 255) / 256, 256>>>(b1, x1, n, 7);
    // 4) S2T = (x1 @ W2)^T  (3-pass)
    gemm_hmma<128,64,4,2,3><<<dim3(mb, 1, 1), 256, SM_G3>>>(
        x1, hid, w2h, w2l, hid, n, hid, 64, s2t);
    // 5) P2[s] = adj16 @ S2 partials (split-K x4)
    gemm16<128,64,4,2,64><<<dim3(mb, 1, 4), 256, SM_G4>>>(
        adj16, n, s2t, n, n, n, 64, p2);
    // 6) out2 = log_softmax(2^-14 * sum P2 + b2) -> d_out
    reduce2<<<(n + 3) / 4, 128>>>(b2, out2, n, 4);
}

// round 13
// speedup vs baseline: 3.3644x; 1.0137x over previous
#include <cuda_runtime.h>
#include <cuda_fp16.h>
#include <cstdint>

#define DEV_INLINE __device__ __forceinline__

// ------------------------- global scratch (no allocs allowed) -------------------------
__device__ __half g_adj16[100000000];         // adj * 2^14 as fp16 (200 MB)
__device__ __half g_W1T_hi[256 * 512],  g_W1T_lo[256 * 512];
__device__ __half g_W2T_hi[64 * 256],   g_W2T_lo[64 * 256];
__device__ __half g_S1T[256 * 10000];         // S1^T single fp16
__device__ __half g_S2T[64 * 10000];          // S2^T single fp16
__device__ float  g_P1[8 * 10000 * 256];      // GEMM2 split-K partials [s][m][n] (scaled 2^14)
__device__ float  g_P2[8 * 10000 * 64];       // GEMM4 split-K partials [s][m][n] (scaled 2^14)

#define ADJ_SCALE 16384.0f
#define ADJ_INV   (1.0f / 16384.0f)

// ------------------------- helpers -------------------------
DEV_INLINE uint32_t smem_u32(const void* p) { return (uint32_t)__cvta_generic_to_shared(p); }

DEV_INLINE void cp_async16(uint32_t dst, const void* src, int bytes) {
    asm volatile("cp.async.cg.shared.global [%0], [%1], 16, %2;\n"
                 :: "r"(dst), "l"(src), "r"(bytes));
}
DEV_INLINE void cp_commit()  { asm volatile("cp.async.commit_group;\n" ::); }
DEV_INLINE void cp_wait_all(){ asm volatile("cp.async.wait_group 0;\n" ::); }

DEV_INLINE void split2h(float x0, float x1, uint32_t& hh, uint32_t& ll) {
    const __half2 h = __floats2half2_rn(x0, x1);
    const float2 hf = __half22float2(h);
    const __half2 l = __floats2half2_rn(x0 - hf.x, x1 - hf.y);
    hh = *(const uint32_t*)&h;
    ll = *(const uint32_t*)&l;
}

DEV_INLINE void mma_f16(float* c, const uint32_t* a, const uint32_t* b) {
    asm volatile(
        "mma.sync.aligned.m16n8k16.row.col.f32.f16.f16.f32 "
        "{%0,%1,%2,%3}, {%4,%5,%6,%7}, {%8,%9}, {%0,%1,%2,%3};\n"
        : "+f"(c[0]), "+f"(c[1]), "+f"(c[2]), "+f"(c[3])
        : "r"(a[0]), "r"(a[1]), "r"(a[2]), "r"(a[3]), "r"(b[0]), "r"(b[1]));
}

DEV_INLINE void ldsm4(uint32_t addr, uint32_t& r0, uint32_t& r1, uint32_t& r2, uint32_t& r3) {
    asm volatile("ldmatrix.sync.aligned.m8n8.x4.shared.b16 {%0,%1,%2,%3}, [%4];"
                 : "=r"(r0), "=r"(r1), "=r"(r2), "=r"(r3) : "r"(addr));
}

// ------------------------- gemm16: both operands fp16, 1 MMA pass -------------------------
// D[m,n] = sum_k A16[m,k] * BT[n,k].  A16 [M][lda], BT [N][ldb], both K-major fp16.
// Output: P[slice][m][Ntot] fp32 partials.  grid (mBlocks, 1, kSlices).
template <int BM, int BN, int WARPS_M, int WARPS_N, int BKT>
__global__ void __launch_bounds__(WARPS_M * WARPS_N * 32)
gemm16(const __half* __restrict__ A, int lda,
       const __half* __restrict__ B, int ldb,
       int M, int K, int Ntot, float* __restrict__ P)
{
    constexpr int THREADS = WARPS_M * WARPS_N * 32;
    constexpr int WM = BM / WARPS_M;
    constexpr int WN = BN / WARPS_N;
    constexpr int MT = WM / 16;
    constexpr int NT = WN / 8;
    constexpr int ROWB = (BKT + 8) * 2;     // 144 for BKT=64: row starts conflict-free for ldsm
    constexpr int AB = BM * ROWB;
    constexpr int BB = BN * ROWB;
    constexpr int OFF_B = AB;
    constexpr int STAGE = AB + BB;
    constexpr int SEG = BKT / 8;            // 16B segments per row
    constexpr int NAC = BM * SEG / THREADS;
    constexpr int NBC = BN * SEG / THREADS;

    extern __shared__ char sm[];
    const uint32_t smb = smem_u32(sm);

    const int tid  = threadIdx.x;
    const int warp = tid >> 5;
    const int lane = tid & 31;
    const int wm = warp / WARPS_N;
    const int wn = warp % WARPS_N;
    const int g  = lane >> 2;
    const int tg = lane & 3;

    const int aq_m = (lane & 7) + ((lane >> 3) & 1) * 8;
    const int aq_k = ((lane >> 4) & 1) * 8;
    const int bq_n = (lane & 7) + ((lane >> 4) & 1) * 8;
    const int bq_k = ((lane >> 3) & 1) * 8;

    const int m0 = blockIdx.x * BM;

    const int KS = gridDim.z, sl = blockIdx.z;
    const int nChTot = (K + BKT - 1) / BKT;
    const int cs = sl * nChTot / KS;
    const int ce = (sl + 1) * nChTot / KS;
    const int kB = cs * BKT;
    const int kE = min(ce * BKT, K);
    const int nCh = ce - cs;
    P += (size_t)sl * M * Ntot;

    float acc[MT][NT][4];
    #pragma unroll
    for (int i = 0; i < MT; i++)
        #pragma unroll
        for (int j = 0; j < NT; j++)
            #pragma unroll
            for (int r = 0; r < 4; r++) acc[i][j][r] = 0.0f;

    auto ld = [&](int c, int s) {
        const int k0 = kB + c * BKT;
        #pragma unroll
        for (int i = 0; i < NAC; i++) {
            const int u = tid + i * THREADS;
            const int r = u / SEG, seg = u % SEG;
            const int kk = k0 + seg * 8;
            const int mg = m0 + r;
            const int by = (mg < M && kk + 8 <= kE) ? 16 : 0;
            const int mc = (mg < M) ? mg : (M - 1);
            cp_async16(smb + s * STAGE + r * ROWB + seg * 16,
                       A + (size_t)mc * lda + kk, by);
        }
        #pragma unroll
        for (int i = 0; i < NBC; i++) {
            const int u = tid + i * THREADS;
            const int r = u / SEG, seg = u % SEG;
            const int kk = k0 + seg * 8;
            const int by = (kk + 8 <= kE) ? 16 : 0;
            cp_async16(smb + s * STAGE + OFF_B + r * ROWB + seg * 16,
                       B + (size_t)r * ldb + kk, by);
        }
        cp_commit();
    };

    // prologue
    ld(0, 0);
    cp_wait_all();
    __syncthreads();

    for (int c = 0; c < nCh; c++) {
        const int s = c & 1;
        if (c + 1 < nCh) ld(c + 1, s ^ 1);

        const uint32_t base = smb + s * STAGE;
        #pragma unroll
        for (int kk = 0; kk < BKT; kk += 16) {
            uint32_t ah[MT][4];
            const uint32_t aAddr = base + (wm * WM + aq_m) * ROWB + (kk + aq_k) * 2;
            #pragma unroll
            for (int mt = 0; mt < MT; mt++)
                ldsm4(aAddr + mt * 16 * ROWB, ah[mt][0], ah[mt][1], ah[mt][2], ah[mt][3]);
            const uint32_t bAddr = base + OFF_B + (wn * WN + bq_n) * ROWB + (kk + bq_k) * 2;
            #pragma unroll
            for (int p = 0; p < NT / 2; p++) {
                uint32_t bh[4];
                ldsm4(bAddr + p * 16 * ROWB, bh[0], bh[1], bh[2], bh[3]);
                #pragma unroll
                for (int h = 0; h < 2; h++) {
                    const int nt = 2 * p + h;
                    #pragma unroll
                    for (int mt = 0; mt < MT; mt++)
                        mma_f16(acc[mt][nt], ah[mt], bh + 2 * h);
                }
            }
        }

        if (c + 1 < nCh) cp_wait_all();
        __syncthreads();
    }

    // epilogue: fp32 partials
    #pragma unroll
    for (int mt = 0; mt < MT; mt++) {
        const int r0 = m0 + wm * WM + mt * 16 + g;
        const int r1 = r0 + 8;
        #pragma unroll
        for (int nt = 0; nt < NT; nt++) {
            const int col = wn * WN + nt * 8 + 2 * tg;
            if (r0 < M) *(float2*)(P + (size_t)r0 * Ntot + col) = make_float2(acc[mt][nt][0], acc[mt][nt][1]);
            if (r1 < M) *(float2*)(P + (size_t)r1 * Ntot + col) = make_float2(acc[mt][nt][2], acc[mt][nt][3]);
        }
    }
}

// ------------------------- gemm_hmma: fp32 A (3-pass hi/lo), for G1/G3 -------------------------
// C[n][m] single fp16 (transposed, ld = M).
template <int BM, int BN, int WARPS_M, int WARPS_N>
__global__ void __launch_bounds__(WARPS_M * WARPS_N * 32)
gemm_hmma(const float* __restrict__ A, int lda,
          const __half* __restrict__ Bhi, const __half* __restrict__ Blo, int ldb,
          int M, int K, int Ntot, __half* __restrict__ C)
{
    constexpr int BK = 32;
    constexpr int THREADS = WARPS_M * WARPS_N * 32;
    constexpr int WM = BM / WARPS_M;
    constexpr int WN = BN / WARPS_N;
    constexpr int MT = WM / 16;
    constexpr int NT = WN / 8;
    constexpr int ROWB = 80;
    constexpr int AB   = BM * ROWB;
    constexpr int BB   = BN * ROWB;
    constexpr int OFF_ALO = AB;
    constexpr int OFF_BHI = 2 * AB;
    constexpr int STAGE = 2 * AB + 2 * BB;
    constexpr int NF4 = (BM * BK / 4) / THREADS;
    constexpr int NBC = (BN * 4) / THREADS;

    extern __shared__ char sm[];
    const uint32_t smb = smem_u32(sm);

    const int tid  = threadIdx.x;
    const int warp = tid >> 5;
    const int lane = tid & 31;
    const int wm = warp / WARPS_N;
    const int wn = warp % WARPS_N;
    const int g  = lane >> 2;
    const int tg = lane & 3;

    const int aq_m = (lane & 7) + ((lane >> 3) & 1) * 8;
    const int aq_k = ((lane >> 4) & 1) * 8;
    const int bq_n = (lane & 7) + ((lane >> 4) & 1) * 8;
    const int bq_k = ((lane >> 3) & 1) * 8;

    const int m0 = blockIdx.x * BM;
    const int n0 = blockIdx.y * BN;
    Bhi += (size_t)n0 * ldb;
    Blo += (size_t)n0 * ldb;

    const int nCh = (K + BK - 1) / BK;

    float acc[MT][NT][4];
    #pragma unroll
    for (int i = 0; i < MT; i++)
        #pragma unroll
        for (int j = 0; j < NT; j++)
            #pragma unroll
            for (int r = 0; r < 4; r++) acc[i][j][r] = 0.0f;

    float4 aReg[NF4];

    auto ldA = [&](int c) {
        const int k0 = c * BK;
        #pragma unroll
        for (int i = 0; i < NF4; i++) {
            const int u = tid + i * THREADS;
            const int r = u >> 3, c4 = u & 7;
            const int mg = m0 + r, kg = k0 + c4 * 4;
            aReg[i] = (mg < M && kg < K) ? *(const float4*)(A + (size_t)mg * lda + kg)
                                         : make_float4(0.f, 0.f, 0.f, 0.f);
        }
    };
    auto stA = [&](int s) {
        char* base = sm + s * STAGE;
        #pragma unroll
        for (int i = 0; i < NF4; i++) {
            const int u = tid + i * THREADS;
            const int r = u >> 3, c4 = u & 7;
            const int off = r * ROWB + c4 * 8;
            uint32_t h0, l0, h1, l1;
            split2h(aReg[i].x, aReg[i].y, h0, l0);
            split2h(aReg[i].z, aReg[i].w, h1, l1);
            *(uint2*)(base + off)            = make_uint2(h0, h1);
            *(uint2*)(base + OFF_ALO + off)  = make_uint2(l0, l1);
        }
    };
    auto ldB = [&](int c, int s) {
        const int k0 = c * BK;
        #pragma unroll
        for (int i = 0; i < NBC; i++) {
            const int u = tid + i * THREADS;
            const int n = u >> 2, seg = u & 3;
            const int kk = k0 + seg * 8;
            const int by = (kk + 8 <= K) ? 16 : 0;
            const uint32_t dst = smb + s * STAGE + OFF_BHI + n * ROWB + seg * 16;
            cp_async16(dst, Bhi + (size_t)n * ldb + kk, by);
            cp_async16(dst + BB, Blo + (size_t)n * ldb + kk, by);
        }
        cp_commit();
    };

    ldA(0);
    ldB(0, 0);
    cp_wait_all();
    stA(0);
    __syncthreads();

    for (int c = 0; c < nCh; c++) {
        const int s = c & 1;
        if (c + 1 < nCh) { ldA(c + 1); ldB(c + 1, s ^ 1); }

        const uint32_t base = smb + s * STAGE;
        #pragma unroll
        for (int kk = 0; kk < BK; kk += 16) {
            uint32_t ah[MT][4], al[MT][4];
            const uint32_t aAddr = base + (wm * WM + aq_m) * ROWB + (kk + aq_k) * 2;
            #pragma unroll
            for (int mt = 0; mt < MT; mt++) {
                ldsm4(aAddr + mt * 16 * ROWB,           ah[mt][0], ah[mt][1], ah[mt][2], ah[mt][3]);
                ldsm4(aAddr + mt * 16 * ROWB + OFF_ALO, al[mt][0], al[mt][1], al[mt][2], al[mt][3]);
            }
            const uint32_t bAddr = base + OFF_BHI + (wn * WN + bq_n) * ROWB + (kk + bq_k) * 2;
            #pragma unroll
            for (int p = 0; p < NT / 2; p++) {
                uint32_t bh[4], bl[4];
                ldsm4(bAddr + p * 16 * ROWB,      bh[0], bh[1], bh[2], bh[3]);
                ldsm4(bAddr + p * 16 * ROWB + BB, bl[0], bl[1], bl[2], bl[3]);
                #pragma unroll
                for (int h = 0; h < 2; h++) {
                    const int nt = 2 * p + h;
                    #pragma unroll
                    for (int mt = 0; mt < MT; mt++) {
                        mma_f16(acc[mt][nt], ah[mt], bh + 2 * h);
                        mma_f16(acc[mt][nt], ah[mt], bl + 2 * h);
                        mma_f16(acc[mt][nt], al[mt], bh + 2 * h);
                    }
                }
            }
        }

        if (c + 1 < nCh) { cp_wait_all(); stA(s ^ 1); }
        __syncthreads();
    }

    // epilogue: single fp16 transposed
    #pragma unroll
    for (int mt = 0; mt < MT; mt++) {
        const int r0 = m0 + wm * WM + mt * 16 + g;
        const int r1 = r0 + 8;
        #pragma unroll
        for (int nt = 0; nt < NT; nt++) {
            const int col = n0 + wn * WN + nt * 8 + 2 * tg;
            if (r0 < M) {
                C[(size_t)col * M + r0]       = __float2half(acc[mt][nt][0]);
                C[(size_t)(col + 1) * M + r0] = __float2half(acc[mt][nt][1]);
            }
            if (r1 < M) {
                C[(size_t)col * M + r1]       = __float2half(acc[mt][nt][2]);
                C[(size_t)(col + 1) * M + r1] = __float2half(acc[mt][nt][3]);
            }
        }
    }
}

// ------------------------- prep: adj -> fp16 (scaled 2^14) -------------------------
__global__ void prep_adj(const float* __restrict__ adj, int total8)
{
    const int i = blockIdx.x * blockDim.x + threadIdx.x;
    if (i >= total8) return;
    const float4* s = (const float4*)adj + 2 * (size_t)i;
    const float4 a = s[0], b = s[1];
    const __half2 h0 = __floats2half2_rn(a.x * ADJ_SCALE, a.y * ADJ_SCALE);
    const __half2 h1 = __floats2half2_rn(a.z * ADJ_SCALE, a.w * ADJ_SCALE);
    const __half2 h2 = __floats2half2_rn(b.x * ADJ_SCALE, b.y * ADJ_SCALE);
    const __half2 h3 = __floats2half2_rn(b.z * ADJ_SCALE, b.w * ADJ_SCALE);
    uint4 v;
    v.x = *(const uint32_t*)&h0; v.y = *(const uint32_t*)&h1;
    v.z = *(const uint32_t*)&h2; v.w = *(const uint32_t*)&h3;
    ((uint4*)g_adj16)[i] = v;
}

// ------------------------- prep: W1/W2 -> transposed fp16 hi/lo -------------------------
__global__ void prep_weights(const float* __restrict__ W1, const float* __restrict__ W2)
{
    const int i = blockIdx.x * blockDim.x + threadIdx.x;
    if (i < 512 * 256) {
        const int k = i / 256, n = i % 256;
        const float v = W1[i];
        const __half h = __float2half_rn(v);
        g_W1T_hi[n * 512 + k] = h;
        g_W1T_lo[n * 512 + k] = __float2half_rn(v - __half2float(h));
    }
    if (i < 256 * 64) {
        const int k = i / 64, n = i % 64;
        const float v = W2[i];
        const __half h = __float2half_rn(v);
        g_W2T_hi[n * 256 + k] = h;
        g_W2T_lo[n * 256 + k] = __float2half_rn(v - __half2float(h));
    }
}

// ------------------------- reduce1: x1 = relu(inv*sum_s P1 + b1) -------------------------
__global__ void reduce1(const float* __restrict__ b1, float* __restrict__ x1, int M, int KS)
{
    const int i = blockIdx.x * blockDim.x + threadIdx.x;   // float4 index
    const int tot = M * 64;
    if (i >= tot) return;
    const float4* P = (const float4*)g_P1;
    float4 v = P[i];
    for (int s = 1; s < KS; s++) {
        const float4 w = P[(size_t)s * tot + i];
        v.x += w.x; v.y += w.y; v.z += w.z; v.w += w.w;
    }
    const float4 b = ((const float4*)b1)[i & 63];
    v.x = fmaxf(v.x * ADJ_INV + b.x, 0.f); v.y = fmaxf(v.y * ADJ_INV + b.y, 0.f);
    v.z = fmaxf(v.z * ADJ_INV + b.z, 0.f); v.w = fmaxf(v.w * ADJ_INV + b.w, 0.f);
    ((float4*)x1)[i] = v;
}

// ------------------------- reduce2: out2 = log_softmax(inv*sum_s P2 + b2) -------------------------
__global__ void reduce2(const float* __restrict__ b2, float* __restrict__ out2, int M, int KS)
{
    const int row = blockIdx.x * (blockDim.x >> 5) + (threadIdx.x >> 5);
    if (row >= M) return;
    const int lane = threadIdx.x & 31;
    const size_t tot = (size_t)M * 64;
    float v0 = 0.f, v1 = 0.f;
    for (int s = 0; s < KS; s++) {
        v0 += g_P2[s * tot + (size_t)row * 64 + lane];
        v1 += g_P2[s * tot + (size_t)row * 64 + lane + 32];
    }
    v0 = v0 * ADJ_INV + b2[lane];
    v1 = v1 * ADJ_INV + b2[lane + 32];
    float mx = fmaxf(v0, v1);
    #pragma unroll
    for (int o = 16; o > 0; o >>= 1) mx = fmaxf(mx, __shfl_xor_sync(0xffffffffu, mx, o));
    float ssum = __expf(v0 - mx) + __expf(v1 - mx);
    #pragma unroll
    for (int o = 16; o > 0; o >>= 1) ssum += __shfl_xor_sync(0xffffffffu, ssum, o);
    const float lse = mx + __logf(ssum);
    out2[(size_t)row * 64 + lane]      = v0 - lse;
    out2[(size_t)row * 64 + lane + 32] = v1 - lse;
}

// ------------------------- host -------------------------
extern "C" void kernel_launch(void* const* d_in, const int* in_sizes, int n_in,
                              void* d_out, int out_size)
{
    const float* feature = (const float*)d_in[0];
    const float* adj     = (const float*)d_in[1];
    const float* W1      = (const float*)d_in[2];
    const float* b1      = (const float*)d_in[3];
    const float* W2      = (const float*)d_in[4];
    const float* b2      = (const float*)d_in[5];

    const int hid  = in_sizes[3];              // 256
    const int fin  = in_sizes[2] / hid;        // 512
    const int n    = in_sizes[0] / fin;        // 10000

    // smem sizes
    constexpr int SM_G1 = 2 * (2 * 128 * 80 + 2 * 128 * 80);    //  81920 (3-pass, BN=128, BK=32)
    constexpr int SM_G2 = 2 * (128 * 144 + 256 * 144);          // 110592 (fp16x2, BN=256, BK=64)
    constexpr int SM_G3 = 2 * (2 * 128 * 80 + 2 * 64 * 80);     //  61440 (3-pass, BN=64, BK=32)
    constexpr int SM_G4 = 2 * (128 * 144 + 64 * 144);           //  55296 (fp16x2, BN=64, BK=64)
    cudaFuncSetAttribute((const void*)gemm_hmma<128,128,4,2>, cudaFuncAttributeMaxDynamicSharedMemorySize, SM_G1);
    cudaFuncSetAttribute((const void*)gemm16<128,256,2,8,64>, cudaFuncAttributeMaxDynamicSharedMemorySize, SM_G2);
    cudaFuncSetAttribute((const void*)gemm_hmma<128,64,4,2>,  cudaFuncAttributeMaxDynamicSharedMemorySize, SM_G3);
    cudaFuncSetAttribute((const void*)gemm16<128,64,4,4,64>,  cudaFuncAttributeMaxDynamicSharedMemorySize, SM_G4);

    __half *adj16, *w1h, *w1l, *w2h, *w2l, *s1t, *s2t;
    float *p1, *p2;
    cudaGetSymbolAddress((void**)&adj16, g_adj16);
    cudaGetSymbolAddress((void**)&w1h, g_W1T_hi); cudaGetSymbolAddress((void**)&w1l, g_W1T_lo);
    cudaGetSymbolAddress((void**)&w2h, g_W2T_hi); cudaGetSymbolAddress((void**)&w2l, g_W2T_lo);
    cudaGetSymbolAddress((void**)&s1t, g_S1T);    cudaGetSymbolAddress((void**)&s2t, g_S2T);
    cudaGetSymbolAddress((void**)&p1, g_P1);      cudaGetSymbolAddress((void**)&p2, g_P2);

    float* x1   = (float*)d_out;               // [n, 256]
    float* out2 = x1 + (size_t)n * hid;        // [n, 64]
    const int mb = (n + 127) / 128;            // 79

    // 0) preps: weights -> fp16 hi/lo; adj -> fp16 (scaled)
    prep_weights<<<512, 256>>>(W1, W2);
    const int total8 = (n * n) / 8;
    prep_adj<<<(total8 + 255) / 256, 256>>>(adj, total8);
    // 1) S1T = (feature @ W1)^T  (3-pass, near-fp32; out single fp16)
    gemm_hmma<128,128,4,2><<<dim3(mb, 2, 1), 256, SM_G1>>>(
        feature, fin, w1h, w1l, fin, n, fin, hid, s1t);
    // 2) P1[s] = adj16 @ S1 partials (fp16 x fp16; 512 thr, 16 warps; split-K x7)
    gemm16<128,256,2,8,64><<<dim3(mb, 1, 7), 512, SM_G2>>>(
        adj16, n, s1t, n, n, n, hid, p1);
    // 3) x1 = relu(2^-14 * sum P1 + b1) -> d_out
    reduce1<<<(n * 64 + 255) / 256, 256>>>(b1, x1, n, 7);
    // 4) S2T = (x1 @ W2)^T  (3-pass)
    gemm_hmma<128,64,4,2><<<dim3(mb, 1, 1), 256, SM_G3>>>(
        x1, hid, w2h, w2l, hid, n, hid, 64, s2t);
    // 5) P2[s] = adj16 @ S2 partials (512 thr; split-K x8)
    gemm16<128,64,4,4,64><<<dim3(mb, 1, 8), 512, SM_G4>>>(
        adj16, n, s2t, n, n, n, 64, p2);
    // 6) out2 = log_softmax(2^-14 * sum P2 + b2) -> d_out
    reduce2<<<(n + 3) / 4, 128>>>(b2, out2, n, 8);
}